// round 6
// baseline (speedup 1.0000x reference)
#include <cuda_runtime.h>
#include <cstdint>

// ---------------- problem constants ----------------
#define N1 120000
#define N2 20000
#define N3 4000
#define E0C 1800000
#define E1C 200000
#define E2C 20000
#define FIN 128
#define FH  256
#define FC  47

// ---------------- device scratch ----------------
__device__ float g_xr[(size_t)N1 * FIN];        // tf32-rounded self features, layer0
__device__ float g_mean0[(size_t)N1 * FIN];
__device__ float g_h1[(size_t)N1 * FH];
__device__ float g_mean1[(size_t)N2 * FH];
__device__ float g_h2[(size_t)N2 * FH];
__device__ float g_mean2[(size_t)N3 * FH];
// split, tf32-rounded weights: self [DIN][DOUTP], mean [DIN][DOUTP]
__device__ float g_W0s[128 * 256], g_W0n[128 * 256];
__device__ float g_W1s[256 * 256], g_W1n[256 * 256];
__device__ float g_W2s[256 * 64],  g_W2n[256 * 64];
// sort scratch
__device__ int g_cnt0[N1], g_cur0[N1], g_starts0[N1 + 1], g_bsum0[512];
__device__ int g_cnt1[N2], g_cur1[N2], g_starts1[N2 + 1], g_bsum1[512];
__device__ int g_cnt2[N3], g_cur2[N3], g_starts2[N3 + 1], g_bsum2[512];
__device__ int g_ssrc0[E0C], g_ssrc1[E1C], g_ssrc2[E2C];

#define NB0 ((N1 + 255) / 256)
#define NB1 ((N2 + 255) / 256)
#define NB2 ((N3 + 255) / 256)

// ---------------- helpers ----------------
__device__ __forceinline__ uint32_t tf32u(float x) {
    uint32_t u; asm("cvt.rna.tf32.f32 %0, %1;" : "=r"(u) : "f"(x)); return u;
}
__device__ __forceinline__ float tf32f(float x) { return __uint_as_float(tf32u(x)); }
__device__ __forceinline__ uint32_t smem_u32(const void* p) {
    uint32_t a;
    asm("{ .reg .u64 t; cvta.to.shared.u64 t, %1; cvt.u32.u64 %0, t; }" : "=r"(a) : "l"(p));
    return a;
}
__device__ __forceinline__ void cp_async16(uint32_t saddr, const void* g, int sz) {
    asm volatile("cp.async.cg.shared.global [%0], [%1], 16, %2;"
                 :: "r"(saddr), "l"(g), "r"(sz) : "memory");
}
__device__ __forceinline__ void cp_commit() {
    asm volatile("cp.async.commit_group;" ::: "memory");
}
template <int N>
__device__ __forceinline__ void cp_wait() {
    asm volatile("cp.async.wait_group %0;" :: "n"(N) : "memory");
}
__device__ __forceinline__ void mma16n8k8(float& c0, float& c1, float& c2, float& c3,
                                          uint32_t a0, uint32_t a1, uint32_t a2, uint32_t a3,
                                          uint32_t b0, uint32_t b1) {
    asm("mma.sync.aligned.m16n8k8.row.col.f32.tf32.tf32.f32 "
        "{%0,%1,%2,%3}, {%4,%5,%6,%7}, {%8,%9}, {%0,%1,%2,%3};"
        : "+f"(c0), "+f"(c1), "+f"(c2), "+f"(c3)
        : "r"(a0), "r"(a1), "r"(a2), "r"(a3), "r"(b0), "r"(b1));
}

// ---------------- zero counters ----------------
__global__ void zero_counters() {
    int i = blockIdx.x * blockDim.x + threadIdx.x;
    int stride = gridDim.x * blockDim.x;
    for (int j = i; j < N1; j += stride) { g_cnt0[j] = 0; g_cur0[j] = 0; }
    for (int j = i; j < N2; j += stride) { g_cnt1[j] = 0; g_cur1[j] = 0; }
    for (int j = i; j < N3; j += stride) { g_cnt2[j] = 0; g_cur2[j] = 0; }
}

// ---------------- prep: round x[:N1] + split/round weights ----------------
__global__ void prep_kernel(const float* __restrict__ x,
                            const float* __restrict__ Ws0, const float* __restrict__ Wn0,
                            const float* __restrict__ Ws1, const float* __restrict__ Wn1,
                            const float* __restrict__ Ws2, const float* __restrict__ Wn2) {
    int i0 = blockIdx.x * blockDim.x + threadIdx.x;
    int stride = gridDim.x * blockDim.x;
    for (int i = i0; i < N1 * FIN; i += stride) g_xr[i] = tf32f(x[i]);
    for (int i = i0; i < 128 * 256; i += stride) {
        g_W0s[i] = tf32f(Ws0[i]);
        g_W0n[i] = tf32f(Wn0[i]);
    }
    for (int i = i0; i < 256 * 256; i += stride) {
        g_W1s[i] = tf32f(Ws1[i]);
        g_W1n[i] = tf32f(Wn1[i]);
    }
    for (int i = i0; i < 256 * 64; i += stride) {
        int k = i >> 6, c = i & 63;
        g_W2s[i] = (c < FC) ? tf32f(Ws2[k * FC + c]) : 0.f;
        g_W2n[i] = (c < FC) ? tf32f(Wn2[k * FC + c]) : 0.f;
    }
}

// ---------------- histogram over all 3 edge lists ----------------
__global__ void hist_all(const int* __restrict__ d0, int nE0,
                         const int* __restrict__ d1, int nE1,
                         const int* __restrict__ d2, int nE2) {
    int i = blockIdx.x * blockDim.x + threadIdx.x;
    if (i < nE0)                    atomicAdd(&g_cnt0[__ldg(d0 + i)], 1);
    else if (i < nE0 + nE1)         atomicAdd(&g_cnt1[__ldg(d1 + i - nE0)], 1);
    else if (i < nE0 + nE1 + nE2)   atomicAdd(&g_cnt2[__ldg(d2 + i - nE0 - nE1)], 1);
}

// ---------------- fused scans (all 3 layers per stage) ----------------
__global__ void scan_block_all() {
    __shared__ int s[256];
    int b = blockIdx.x;
    const int* cnt; int n, lb; int* starts; int* bsum;
    if (b < NB0)            { cnt = g_cnt0; n = N1; starts = g_starts0; bsum = g_bsum0; lb = b; }
    else if (b < NB0 + NB1) { cnt = g_cnt1; n = N2; starts = g_starts1; bsum = g_bsum1; lb = b - NB0; }
    else                    { cnt = g_cnt2; n = N3; starts = g_starts2; bsum = g_bsum2; lb = b - NB0 - NB1; }
    int i = lb * 256 + threadIdx.x;
    int v = (i < n) ? cnt[i] : 0;
    s[threadIdx.x] = v;
    __syncthreads();
    for (int off = 1; off < 256; off <<= 1) {
        int t = (threadIdx.x >= off) ? s[threadIdx.x - off] : 0;
        __syncthreads();
        s[threadIdx.x] += t;
        __syncthreads();
    }
    if (i < n) starts[i] = s[threadIdx.x] - v;   // exclusive
    if (threadIdx.x == 255) bsum[lb] = s[255];
}
__global__ void scan_bsum_all() {
    __shared__ int s[512];
    int* bsum; int nb;
    if (blockIdx.x == 0)      { bsum = g_bsum0; nb = NB0; }
    else if (blockIdx.x == 1) { bsum = g_bsum1; nb = NB1; }
    else                      { bsum = g_bsum2; nb = NB2; }
    int v = (threadIdx.x < nb) ? bsum[threadIdx.x] : 0;
    s[threadIdx.x] = v;
    __syncthreads();
    for (int off = 1; off < 512; off <<= 1) {
        int t = (threadIdx.x >= off) ? s[threadIdx.x - off] : 0;
        __syncthreads();
        s[threadIdx.x] += t;
        __syncthreads();
    }
    if (threadIdx.x < nb) bsum[threadIdx.x] = s[threadIdx.x] - v;  // exclusive
}
__global__ void scan_add_all(int nE0, int nE1, int nE2) {
    int b = blockIdx.x;
    int* starts; const int* bsum; int n, nE, lb;
    if (b < NB0)            { starts = g_starts0; bsum = g_bsum0; n = N1; nE = nE0; lb = b; }
    else if (b < NB0 + NB1) { starts = g_starts1; bsum = g_bsum1; n = N2; nE = nE1; lb = b - NB0; }
    else                    { starts = g_starts2; bsum = g_bsum2; n = N3; nE = nE2; lb = b - NB0 - NB1; }
    int i = lb * 256 + threadIdx.x;
    if (i < n) starts[i] += bsum[lb];
    if (lb == 0 && threadIdx.x == 0) starts[n] = nE;
}

// ---------------- permute srcs into dst-sorted order ----------------
__global__ void permute_all(const int* __restrict__ s0, const int* __restrict__ d0, int nE0,
                            const int* __restrict__ s1, const int* __restrict__ d1, int nE1,
                            const int* __restrict__ s2, const int* __restrict__ d2, int nE2) {
    int i = blockIdx.x * blockDim.x + threadIdx.x;
    if (i < nE0) {
        int d = __ldg(d0 + i);
        g_ssrc0[g_starts0[d] + atomicAdd(&g_cur0[d], 1)] = __ldg(s0 + i);
    } else if (i < nE0 + nE1) {
        int e = i - nE0, d = __ldg(d1 + e);
        g_ssrc1[g_starts1[d] + atomicAdd(&g_cur1[d], 1)] = __ldg(s1 + e);
    } else if (i < nE0 + nE1 + nE2) {
        int e = i - nE0 - nE1, d = __ldg(d2 + e);
        g_ssrc2[g_starts2[d] + atomicAdd(&g_cur2[d], 1)] = __ldg(s2 + e);
    }
}

// ---------------- segmented mean aggregation: one warp per dst node ----------------
template <int DIN>
__global__ void agg_kernel(const float* __restrict__ h, const int* __restrict__ ssrc,
                           const int* __restrict__ starts, int nD,
                           float* __restrict__ mean) {
    constexpr int NF4 = DIN / 128;
    int w = (int)((blockIdx.x * (unsigned)blockDim.x + threadIdx.x) >> 5);
    int lane = threadIdx.x & 31;
    if (w >= nD) return;
    int beg = __ldg(starts + w), end = __ldg(starts + w + 1);
    float4 acc[NF4];
#pragma unroll
    for (int j = 0; j < NF4; j++) acc[j] = make_float4(0.f, 0.f, 0.f, 0.f);
    int i = beg;
    for (; i + 2 <= end; i += 2) {
        int s0 = __ldg(ssrc + i), s1 = __ldg(ssrc + i + 1);
        float4 a[NF4], b[NF4];
#pragma unroll
        for (int j = 0; j < NF4; j++)
            a[j] = __ldg((const float4*)(h + (size_t)s0 * DIN) + lane + j * 32);
#pragma unroll
        for (int j = 0; j < NF4; j++)
            b[j] = __ldg((const float4*)(h + (size_t)s1 * DIN) + lane + j * 32);
#pragma unroll
        for (int j = 0; j < NF4; j++) {
            acc[j].x += a[j].x + b[j].x; acc[j].y += a[j].y + b[j].y;
            acc[j].z += a[j].z + b[j].z; acc[j].w += a[j].w + b[j].w;
        }
    }
    if (i < end) {
        int s0 = __ldg(ssrc + i);
#pragma unroll
        for (int j = 0; j < NF4; j++) {
            float4 a = __ldg((const float4*)(h + (size_t)s0 * DIN) + lane + j * 32);
            acc[j].x += a.x; acc[j].y += a.y; acc[j].z += a.z; acc[j].w += a.w;
        }
    }
    float inv = (end > beg) ? (1.0f / (float)(end - beg)) : 0.0f;
#pragma unroll
    for (int j = 0; j < NF4; j++) {
        float4 o;
        o.x = tf32f(acc[j].x * inv); o.y = tf32f(acc[j].y * inv);
        o.z = tf32f(acc[j].z * inv); o.w = tf32f(acc[j].w * inv);
        *((float4*)(mean + (size_t)w * DIN) + lane + j * 32) = o;
    }
}

// ---------------- GEMM: cp.async double-buffered mma.sync tf32 ----------------
// FINAL=false: C = A @ W                  (raw overwrite)
// FINAL=true:  C = [round](act(C + A @ W + bias))
// BM=128 x BN=128 x BK=32, 256 thr = 8 warps (warp tile 32x64), operands pre-rounded.
template <int K, int DOUTP, bool FINAL, bool RELU, bool ROUND_OUT>
__global__ void __launch_bounds__(256, 2)
sage_gemm(const float* __restrict__ A, const float* __restrict__ W,
          const float* __restrict__ bias, float* __restrict__ C, int n, int dout) {
    constexpr int NCH = K / 32;
    constexpr int SA_STRIDE = 36;
    constexpr int SB_STRIDE = 136;
    constexpr int SA_ELEMS = 128 * SA_STRIDE;
    constexpr int SB_ELEMS = 32 * SB_STRIDE;
    extern __shared__ uint32_t smem[];
    uint32_t* sA[2] = { smem, smem + SA_ELEMS };
    uint32_t* sB[2] = { smem + 2 * SA_ELEMS, smem + 2 * SA_ELEMS + SB_ELEMS };
    const uint32_t sA32[2] = { smem_u32(sA[0]), smem_u32(sA[1]) };
    const uint32_t sB32[2] = { smem_u32(sB[0]), smem_u32(sB[1]) };

    const int tid  = threadIdx.x;
    const int lane = tid & 31, wid = tid >> 5;
    const int gid  = lane >> 2, tig = lane & 3;
    const int row0 = blockIdx.x * 128, col0 = blockIdx.y * 128;
    const int wr = wid & 3, wc = wid >> 2;

    auto issue = [&](int kc, int buf) {
        const int k0 = kc * 32;
#pragma unroll
        for (int it = 0; it < 4; it++) {
            int f = tid + it * 256;
            int r = f >> 3, c4 = (f & 7) * 4;
            bool ok = (row0 + r) < n;
            const float* g = A + (ok ? ((size_t)(row0 + r) * K + k0 + c4) : 0);
            cp_async16(sA32[buf] + (uint32_t)(r * SA_STRIDE + c4) * 4u, g, ok ? 16 : 0);
        }
#pragma unroll
        for (int it = 0; it < 4; it++) {
            int f = tid + it * 256;
            int k = f >> 5, c4 = (f & 31) * 4;
            bool ok = (col0 + c4) < DOUTP;
            const float* g = W + (ok ? ((size_t)(k0 + k) * DOUTP + col0 + c4) : 0);
            cp_async16(sB32[buf] + (uint32_t)(k * SB_STRIDE + c4) * 4u, g, ok ? 16 : 0);
        }
        cp_commit();
    };

    float acc[2][8][4];
#pragma unroll
    for (int mi = 0; mi < 2; mi++)
#pragma unroll
        for (int ni = 0; ni < 8; ni++)
#pragma unroll
            for (int j = 0; j < 4; j++) acc[mi][ni][j] = 0.f;

    issue(0, 0);
    for (int kc = 0; kc < NCH; kc++) {
        const int buf = kc & 1;
        if (kc + 1 < NCH) { issue(kc + 1, buf ^ 1); cp_wait<1>(); }
        else              { cp_wait<0>(); }
        __syncthreads();
        const uint32_t* A_ = sA[buf];
        const uint32_t* B_ = sB[buf];
#pragma unroll
        for (int ks = 0; ks < 4; ks++) {
            const int k = ks * 8;
            uint32_t a[2][4];
#pragma unroll
            for (int mi = 0; mi < 2; mi++) {
                int rb = wr * 32 + mi * 16;
                a[mi][0] = A_[(rb + gid)     * SA_STRIDE + k + tig];
                a[mi][1] = A_[(rb + gid + 8) * SA_STRIDE + k + tig];
                a[mi][2] = A_[(rb + gid)     * SA_STRIDE + k + tig + 4];
                a[mi][3] = A_[(rb + gid + 8) * SA_STRIDE + k + tig + 4];
            }
#pragma unroll
            for (int ni = 0; ni < 8; ni++) {
                int cb = wc * 64 + ni * 8 + gid;
                uint32_t b0 = B_[(k + tig)     * SB_STRIDE + cb];
                uint32_t b1 = B_[(k + tig + 4) * SB_STRIDE + cb];
#pragma unroll
                for (int mi = 0; mi < 2; mi++)
                    mma16n8k8(acc[mi][ni][0], acc[mi][ni][1], acc[mi][ni][2], acc[mi][ni][3],
                              a[mi][0], a[mi][1], a[mi][2], a[mi][3], b0, b1);
            }
        }
        __syncthreads();
    }

    // ---- epilogue ----
#pragma unroll
    for (int mi = 0; mi < 2; mi++) {
        int row = row0 + wr * 32 + mi * 16 + gid;
#pragma unroll
        for (int ni = 0; ni < 8; ni++) {
            int col = col0 + wc * 64 + ni * 8 + tig * 2;
#pragma unroll
            for (int half = 0; half < 2; half++) {
                int r = row + half * 8;
                if (r >= n) continue;
#pragma unroll
                for (int q = 0; q < 2; q++) {
                    int c = col + q;
                    if (c >= dout) continue;
                    float v = acc[mi][ni][half * 2 + q];
                    if (FINAL) {
                        v += C[(size_t)r * dout + c] + __ldg(bias + c);
                        if (RELU) v = fmaxf(v, 0.f);
                        if (ROUND_OUT) v = tf32f(v);
                    }
                    C[(size_t)r * dout + c] = v;
                }
            }
        }
    }
}

// ---------------- host launcher ----------------
extern "C" void kernel_launch(void* const* d_in, const int* in_sizes, int n_in,
                              void* d_out, int out_size) {
    const float* x    = (const float*)d_in[0];
    const int*   src0 = (const int*)d_in[1];
    const int*   dst0 = (const int*)d_in[2];
    const int*   src1 = (const int*)d_in[3];
    const int*   dst1 = (const int*)d_in[4];
    const int*   src2 = (const int*)d_in[5];
    const int*   dst2 = (const int*)d_in[6];
    const float* Ws0  = (const float*)d_in[7];
    const float* Wn0  = (const float*)d_in[8];
    const float* b0   = (const float*)d_in[9];
    const float* Ws1  = (const float*)d_in[10];
    const float* Wn1  = (const float*)d_in[11];
    const float* b1   = (const float*)d_in[12];
    const float* Ws2  = (const float*)d_in[13];
    const float* Wn2  = (const float*)d_in[14];
    const float* b2   = (const float*)d_in[15];
    float* out = (float*)d_out;

    int E0 = in_sizes[1], E1 = in_sizes[3], E2 = in_sizes[5];
    int ET = E0 + E1 + E2;

    float *xr, *mean0, *h1, *mean1, *h2, *mean2;
    float *W0s, *W0n, *W1s, *W1n, *W2s, *W2n;
    int *st0, *st1, *st2, *ss0, *ss1, *ss2;
    cudaGetSymbolAddress((void**)&xr, g_xr);
    cudaGetSymbolAddress((void**)&mean0, g_mean0);
    cudaGetSymbolAddress((void**)&h1, g_h1);
    cudaGetSymbolAddress((void**)&mean1, g_mean1);
    cudaGetSymbolAddress((void**)&h2, g_h2);
    cudaGetSymbolAddress((void**)&mean2, g_mean2);
    cudaGetSymbolAddress((void**)&W0s, g_W0s);
    cudaGetSymbolAddress((void**)&W0n, g_W0n);
    cudaGetSymbolAddress((void**)&W1s, g_W1s);
    cudaGetSymbolAddress((void**)&W1n, g_W1n);
    cudaGetSymbolAddress((void**)&W2s, g_W2s);
    cudaGetSymbolAddress((void**)&W2n, g_W2n);
    cudaGetSymbolAddress((void**)&st0, g_starts0);
    cudaGetSymbolAddress((void**)&st1, g_starts1);
    cudaGetSymbolAddress((void**)&st2, g_starts2);
    cudaGetSymbolAddress((void**)&ss0, g_ssrc0);
    cudaGetSymbolAddress((void**)&ss1, g_ssrc1);
    cudaGetSymbolAddress((void**)&ss2, g_ssrc2);

    const int SMEM = (2 * 128 * 36 + 2 * 32 * 136) * 4;  // 71680 B
    cudaFuncSetAttribute(sage_gemm<128, 256, false, false, false>,
                         cudaFuncAttributeMaxDynamicSharedMemorySize, SMEM);
    cudaFuncSetAttribute(sage_gemm<128, 256, true, true, true>,
                         cudaFuncAttributeMaxDynamicSharedMemorySize, SMEM);
    cudaFuncSetAttribute(sage_gemm<256, 256, false, false, false>,
                         cudaFuncAttributeMaxDynamicSharedMemorySize, SMEM);
    cudaFuncSetAttribute(sage_gemm<256, 256, true, true, true>,
                         cudaFuncAttributeMaxDynamicSharedMemorySize, SMEM);
    cudaFuncSetAttribute(sage_gemm<256, 64, false, false, false>,
                         cudaFuncAttributeMaxDynamicSharedMemorySize, SMEM);
    cudaFuncSetAttribute(sage_gemm<256, 64, true, false, false>,
                         cudaFuncAttributeMaxDynamicSharedMemorySize, SMEM);

    // side stream + events (created once, outside any capture; reused every call)
    static cudaStream_t sSide = nullptr;
    static cudaEvent_t evF0, evJ0, evF1, evJ1, evF2, evJ2;
    if (!sSide) {
        cudaStreamCreateWithFlags(&sSide, cudaStreamNonBlocking);
        cudaEventCreateWithFlags(&evF0, cudaEventDisableTiming);
        cudaEventCreateWithFlags(&evJ0, cudaEventDisableTiming);
        cudaEventCreateWithFlags(&evF1, cudaEventDisableTiming);
        cudaEventCreateWithFlags(&evJ1, cudaEventDisableTiming);
        cudaEventCreateWithFlags(&evF2, cudaEventDisableTiming);
        cudaEventCreateWithFlags(&evJ2, cudaEventDisableTiming);
    }

    // ======== fork: side stream does prep + gemm0_self while main sorts + aggs ========
    cudaEventRecord(evF0, 0);
    cudaStreamWaitEvent(sSide, evF0, 0);

    // main stream: sort pipeline + agg0
    zero_counters<<<160, 256>>>();
    hist_all<<<(ET + 255) / 256, 256>>>(dst0, E0, dst1, E1, dst2, E2);
    scan_block_all<<<NB0 + NB1 + NB2, 256>>>();
    scan_bsum_all<<<3, 512>>>();
    scan_add_all<<<NB0 + NB1 + NB2, 256>>>(E0, E1, E2);
    permute_all<<<(ET + 255) / 256, 256>>>(src0, dst0, E0, src1, dst1, E1, src2, dst2, E2);
    agg_kernel<FIN><<<(N1 * 32 + 255) / 256, 256>>>(x, ss0, st0, N1, mean0);

    // side stream: prep + self-GEMM of layer 0
    prep_kernel<<<1184, 256, 0, sSide>>>(x, Ws0, Wn0, Ws1, Wn1, Ws2, Wn2);
    sage_gemm<128, 256, false, false, false><<<dim3((N1 + 127) / 128, 2), 256, SMEM, sSide>>>(
        xr, W0s, nullptr, h1, N1, FH);
    cudaEventRecord(evJ0, sSide);

    // join + layer0 mean pass
    cudaStreamWaitEvent(0, evJ0, 0);
    sage_gemm<128, 256, true, true, true><<<dim3((N1 + 127) / 128, 2), 256, SMEM>>>(
        mean0, W0n, b0, h1, N1, FH);

    // ======== layer 1: agg1 (main) || gemm1_self (side) ========
    cudaEventRecord(evF1, 0);
    cudaStreamWaitEvent(sSide, evF1, 0);
    sage_gemm<256, 256, false, false, false><<<dim3((N2 + 127) / 128, 2), 256, SMEM, sSide>>>(
        h1, W1s, nullptr, h2, N2, FH);
    cudaEventRecord(evJ1, sSide);
    agg_kernel<FH><<<(N2 * 32 + 255) / 256, 256>>>(h1, ss1, st1, N2, mean1);
    cudaStreamWaitEvent(0, evJ1, 0);
    sage_gemm<256, 256, true, true, true><<<dim3((N2 + 127) / 128, 2), 256, SMEM>>>(
        mean1, W1n, b1, h2, N2, FH);

    // ======== layer 2: agg2 (main) || gemm2_self (side) ========
    cudaEventRecord(evF2, 0);
    cudaStreamWaitEvent(sSide, evF2, 0);
    sage_gemm<256, 64, false, false, false><<<dim3((N3 + 127) / 128, 1), 256, SMEM, sSide>>>(
        h2, W2s, nullptr, out, N3, FC);
    cudaEventRecord(evJ2, sSide);
    agg_kernel<FH><<<(N3 * 32 + 255) / 256, 256>>>(h2, ss2, st2, N3, mean2);
    cudaStreamWaitEvent(0, evJ2, 0);
    sage_gemm<256, 64, true, false, false><<<dim3((N3 + 127) / 128, 1), 256, SMEM>>>(
        mean2, W2n, b2, out, N3, FC);
}

// round 7
// speedup vs baseline: 1.6542x; 1.6542x over previous
#include <cuda_runtime.h>
#include <cuda_fp16.h>
#include <cstdint>

// ---------------- problem constants ----------------
#define N1 120000
#define N2 20000
#define N3 4000
#define E0C 1800000
#define E1C 200000
#define E2C 20000
#define FIN 128
#define FH  256
#define FC  47

// ---------------- device scratch (fp16 features packed as u32 = half2) ----------------
__device__ uint32_t g_xr[(size_t)N1 * FIN / 2];      // x[:N1] in fp16
__device__ uint32_t g_mean0[(size_t)N1 * FIN / 2];
__device__ uint32_t g_h1[(size_t)N1 * FH / 2];
__device__ uint32_t g_mean1[(size_t)N2 * FH / 2];
__device__ uint32_t g_h2[(size_t)N2 * FH / 2];
__device__ uint32_t g_mean2[(size_t)N3 * FH / 2];
// weights pre-packed: Wp[kpair][n] = half2{W[2kp][n], W[2kp+1][n]}, stacked [Ws;Wn]
__device__ uint32_t g_Wp0[128 * 256];
__device__ uint32_t g_Wp1[256 * 256];
__device__ uint32_t g_Wp2[256 * 64];
// sort scratch
__device__ int g_cnt0[N1], g_starts0[N1 + 1], g_bsum0[512];
__device__ int g_cnt1[N2], g_starts1[N2 + 1], g_bsum1[512];
__device__ int g_cnt2[N3], g_starts2[N3 + 1], g_bsum2[512];
__device__ int g_ssrc0[E0C], g_ssrc1[E1C], g_ssrc2[E2C];

#define NB0 ((N1 + 255) / 256)
#define NB1 ((N2 + 255) / 256)
#define NB2 ((N3 + 255) / 256)

// ---------------- helpers ----------------
__device__ __forceinline__ uint32_t smem_u32(const void* p) {
    uint32_t a;
    asm("{ .reg .u64 t; cvta.to.shared.u64 t, %1; cvt.u32.u64 %0, t; }" : "=r"(a) : "l"(p));
    return a;
}
__device__ __forceinline__ void cp_async16(uint32_t saddr, const void* g, int sz) {
    asm volatile("cp.async.cg.shared.global [%0], [%1], 16, %2;"
                 :: "r"(saddr), "l"(g), "r"(sz) : "memory");
}
__device__ __forceinline__ void cp_commit() {
    asm volatile("cp.async.commit_group;" ::: "memory");
}
template <int N>
__device__ __forceinline__ void cp_wait() {
    asm volatile("cp.async.wait_group %0;" :: "n"(N) : "memory");
}
__device__ __forceinline__ uint32_t pack_h2(float lo, float hi) {
    __half2 h = __floats2half2_rn(lo, hi);
    return *(uint32_t*)&h;
}
// m16n8k16 fp16 MMA, fp32 accumulate
__device__ __forceinline__ void mma16n8k16(float& c0, float& c1, float& c2, float& c3,
                                           uint32_t a0, uint32_t a1, uint32_t a2, uint32_t a3,
                                           uint32_t b0, uint32_t b1) {
    asm("mma.sync.aligned.m16n8k16.row.col.f32.f16.f16.f32 "
        "{%0,%1,%2,%3}, {%4,%5,%6,%7}, {%8,%9}, {%0,%1,%2,%3};"
        : "+f"(c0), "+f"(c1), "+f"(c2), "+f"(c3)
        : "r"(a0), "r"(a1), "r"(a2), "r"(a3), "r"(b0), "r"(b1));
}

// ---------------- zero counters ----------------
__global__ void zero_counters() {
    int i = blockIdx.x * blockDim.x + threadIdx.x;
    int stride = gridDim.x * blockDim.x;
    for (int j = i; j < N1; j += stride) g_cnt0[j] = 0;
    for (int j = i; j < N2; j += stride) g_cnt1[j] = 0;
    for (int j = i; j < N3; j += stride) g_cnt2[j] = 0;
}

// ---------------- prep: x -> fp16, weights -> packed fp16 pairs ----------------
__global__ void prep_kernel(const float* __restrict__ x,
                            const float* __restrict__ Ws0, const float* __restrict__ Wn0,
                            const float* __restrict__ Ws1, const float* __restrict__ Wn1,
                            const float* __restrict__ Ws2, const float* __restrict__ Wn2) {
    int i0 = blockIdx.x * blockDim.x + threadIdx.x;
    int stride = gridDim.x * blockDim.x;
    for (int i = i0; i < N1 * FIN / 2; i += stride) {
        float2 v = ((const float2*)x)[i];
        g_xr[i] = pack_h2(v.x, v.y);
    }
    for (int i = i0; i < 128 * 256; i += stride) {       // L0: 128 kpairs x 256
        int kp = i >> 8, c = i & 255;
        float lo, hi;
        if (kp < 64) { lo = Ws0[(2 * kp) * 256 + c];       hi = Ws0[(2 * kp + 1) * 256 + c]; }
        else { int q = kp - 64; lo = Wn0[(2 * q) * 256 + c]; hi = Wn0[(2 * q + 1) * 256 + c]; }
        g_Wp0[i] = pack_h2(lo, hi);
    }
    for (int i = i0; i < 256 * 256; i += stride) {       // L1: 256 kpairs x 256
        int kp = i >> 8, c = i & 255;
        float lo, hi;
        if (kp < 128) { lo = Ws1[(2 * kp) * 256 + c];       hi = Ws1[(2 * kp + 1) * 256 + c]; }
        else { int q = kp - 128; lo = Wn1[(2 * q) * 256 + c]; hi = Wn1[(2 * q + 1) * 256 + c]; }
        g_Wp1[i] = pack_h2(lo, hi);
    }
    for (int i = i0; i < 256 * 64; i += stride) {        // L2: 256 kpairs x 64 (pad 47)
        int kp = i >> 6, c = i & 63;
        float lo = 0.f, hi = 0.f;
        if (c < FC) {
            if (kp < 128) { lo = Ws2[(2 * kp) * FC + c];       hi = Ws2[(2 * kp + 1) * FC + c]; }
            else { int q = kp - 128; lo = Wn2[(2 * q) * FC + c]; hi = Wn2[(2 * q + 1) * FC + c]; }
        }
        g_Wp2[i] = pack_h2(lo, hi);
    }
}

// ---------------- histogram ----------------
__global__ void hist_all(const int* __restrict__ d0, int nE0,
                         const int* __restrict__ d1, int nE1,
                         const int* __restrict__ d2, int nE2) {
    int i = blockIdx.x * blockDim.x + threadIdx.x;
    if (i < nE0)                    atomicAdd(&g_cnt0[__ldg(d0 + i)], 1);
    else if (i < nE0 + nE1)         atomicAdd(&g_cnt1[__ldg(d1 + i - nE0)], 1);
    else if (i < nE0 + nE1 + nE2)   atomicAdd(&g_cnt2[__ldg(d2 + i - nE0 - nE1)], 1);
}

// ---------------- fused scans ----------------
__global__ void scan_block_all() {
    __shared__ int s[256];
    int b = blockIdx.x;
    const int* cnt; int n, lb; int* starts; int* bsum;
    if (b < NB0)            { cnt = g_cnt0; n = N1; starts = g_starts0; bsum = g_bsum0; lb = b; }
    else if (b < NB0 + NB1) { cnt = g_cnt1; n = N2; starts = g_starts1; bsum = g_bsum1; lb = b - NB0; }
    else                    { cnt = g_cnt2; n = N3; starts = g_starts2; bsum = g_bsum2; lb = b - NB0 - NB1; }
    int i = lb * 256 + threadIdx.x;
    int v = (i < n) ? cnt[i] : 0;
    s[threadIdx.x] = v;
    __syncthreads();
    for (int off = 1; off < 256; off <<= 1) {
        int t = (threadIdx.x >= off) ? s[threadIdx.x - off] : 0;
        __syncthreads();
        s[threadIdx.x] += t;
        __syncthreads();
    }
    if (i < n) starts[i] = s[threadIdx.x] - v;
    if (threadIdx.x == 255) bsum[lb] = s[255];
}
__global__ void scan_bsum_all() {
    __shared__ int s[512];
    int* bsum; int nb;
    if (blockIdx.x == 0)      { bsum = g_bsum0; nb = NB0; }
    else if (blockIdx.x == 1) { bsum = g_bsum1; nb = NB1; }
    else                      { bsum = g_bsum2; nb = NB2; }
    int v = (threadIdx.x < nb) ? bsum[threadIdx.x] : 0;
    s[threadIdx.x] = v;
    __syncthreads();
    for (int off = 1; off < 512; off <<= 1) {
        int t = (threadIdx.x >= off) ? s[threadIdx.x - off] : 0;
        __syncthreads();
        s[threadIdx.x] += t;
        __syncthreads();
    }
    if (threadIdx.x < nb) bsum[threadIdx.x] = s[threadIdx.x] - v;
}
__global__ void scan_add_all(int nE0, int nE1, int nE2) {
    int b = blockIdx.x;
    int* starts; const int* bsum; int n, nE, lb;
    if (b < NB0)            { starts = g_starts0; bsum = g_bsum0; n = N1; nE = nE0; lb = b; }
    else if (b < NB0 + NB1) { starts = g_starts1; bsum = g_bsum1; n = N2; nE = nE1; lb = b - NB0; }
    else                    { starts = g_starts2; bsum = g_bsum2; n = N3; nE = nE2; lb = b - NB0 - NB1; }
    int i = lb * 256 + threadIdx.x;
    if (i < n) starts[i] += bsum[lb];
    if (lb == 0 && threadIdx.x == 0) starts[n] = nE;
}

// ---------------- permute (advances starts in place; agg recovers via cnt) ----------------
__global__ void permute_all(const int* __restrict__ s0, const int* __restrict__ d0, int nE0,
                            const int* __restrict__ s1, const int* __restrict__ d1, int nE1,
                            const int* __restrict__ s2, const int* __restrict__ d2, int nE2) {
    int i = blockIdx.x * blockDim.x + threadIdx.x;
    if (i < nE0) {
        int d = __ldg(d0 + i);
        g_ssrc0[atomicAdd(&g_starts0[d], 1)] = __ldg(s0 + i);
    } else if (i < nE0 + nE1) {
        int e = i - nE0, d = __ldg(d1 + e);
        g_ssrc1[atomicAdd(&g_starts1[d], 1)] = __ldg(s1 + e);
    } else if (i < nE0 + nE1 + nE2) {
        int e = i - nE0 - nE1, d = __ldg(d2 + e);
        g_ssrc2[atomicAdd(&g_starts2[d], 1)] = __ldg(s2 + e);
    }
}

// ---------------- agg layer0: fp32 gather -> fp16 mean, DIN=128, warp per node ----------
__global__ void agg0_kernel(const float* __restrict__ x, const int* __restrict__ ssrc,
                            const int* __restrict__ starts, const int* __restrict__ cnt,
                            uint32_t* __restrict__ mean) {
    int w = (int)((blockIdx.x * (unsigned)blockDim.x + threadIdx.x) >> 5);
    int lane = threadIdx.x & 31;
    if (w >= N1) return;
    int end = __ldg(starts + w), c = __ldg(cnt + w), beg = end - c;
    float4 acc = make_float4(0.f, 0.f, 0.f, 0.f);
    int i = beg;
    for (; i + 2 <= end; i += 2) {
        int s0 = __ldg(ssrc + i), s1 = __ldg(ssrc + i + 1);
        float4 a = __ldg((const float4*)(x + (size_t)s0 * FIN) + lane);
        float4 b = __ldg((const float4*)(x + (size_t)s1 * FIN) + lane);
        acc.x += a.x + b.x; acc.y += a.y + b.y; acc.z += a.z + b.z; acc.w += a.w + b.w;
    }
    if (i < end) {
        int s0 = __ldg(ssrc + i);
        float4 a = __ldg((const float4*)(x + (size_t)s0 * FIN) + lane);
        acc.x += a.x; acc.y += a.y; acc.z += a.z; acc.w += a.w;
    }
    float inv = (c > 0) ? (1.0f / (float)c) : 0.0f;
    uint2 o;
    o.x = pack_h2(acc.x * inv, acc.y * inv);
    o.y = pack_h2(acc.z * inv, acc.w * inv);
    *(uint2*)(mean + (size_t)w * (FIN / 2) + lane * 2) = o;
}

// ---------------- agg layers 1/2: fp16 gather -> fp16 mean, DIN=256 -------------------
__global__ void agg12_kernel(const uint32_t* __restrict__ h, const int* __restrict__ ssrc,
                             const int* __restrict__ starts, const int* __restrict__ cnt,
                             int nD, uint32_t* __restrict__ mean) {
    int w = (int)((blockIdx.x * (unsigned)blockDim.x + threadIdx.x) >> 5);
    int lane = threadIdx.x & 31;
    if (w >= nD) return;
    int end = __ldg(starts + w), c = __ldg(cnt + w), beg = end - c;
    float acc[8];
#pragma unroll
    for (int j = 0; j < 8; j++) acc[j] = 0.f;
    int i = beg;
    for (; i + 2 <= end; i += 2) {
        int s0 = __ldg(ssrc + i), s1 = __ldg(ssrc + i + 1);
        uint4 a = __ldg((const uint4*)(h + (size_t)s0 * (FH / 2)) + lane);
        uint4 b = __ldg((const uint4*)(h + (size_t)s1 * (FH / 2)) + lane);
        const uint32_t av[4] = {a.x, a.y, a.z, a.w};
        const uint32_t bv[4] = {b.x, b.y, b.z, b.w};
#pragma unroll
        for (int j = 0; j < 4; j++) {
            float2 fa = __half22float2(*(const __half2*)&av[j]);
            float2 fb = __half22float2(*(const __half2*)&bv[j]);
            acc[2 * j] += fa.x + fb.x; acc[2 * j + 1] += fa.y + fb.y;
        }
    }
    if (i < end) {
        int s0 = __ldg(ssrc + i);
        uint4 a = __ldg((const uint4*)(h + (size_t)s0 * (FH / 2)) + lane);
        const uint32_t av[4] = {a.x, a.y, a.z, a.w};
#pragma unroll
        for (int j = 0; j < 4; j++) {
            float2 fa = __half22float2(*(const __half2*)&av[j]);
            acc[2 * j] += fa.x; acc[2 * j + 1] += fa.y;
        }
    }
    float inv = (c > 0) ? (1.0f / (float)c) : 0.0f;
    uint4 o;
    o.x = pack_h2(acc[0] * inv, acc[1] * inv);
    o.y = pack_h2(acc[2] * inv, acc[3] * inv);
    o.z = pack_h2(acc[4] * inv, acc[5] * inv);
    o.w = pack_h2(acc[6] * inv, acc[7] * inv);
    *((uint4*)(mean + (size_t)w * (FH / 2)) + lane) = o;
}

// ---------------- GEMM: cp.async double-buffered fp16 m16n8k16 ----------------
// C[n, dout] = [self | mean] @ Wp + bias, operands fp16 (packed half2 along k).
// BM=128 x BN=128 x BK=32, 256 thr = 8 warps (warp tile 32x64).
// FINAL=false: fp16 h output (+ReLU).  FINAL=true: fp32 output, no ReLU.
template <int K, int DOUTP, bool FINAL>
__global__ void __launch_bounds__(256, 2)
sage_gemm(const uint32_t* __restrict__ selfp, const uint32_t* __restrict__ meanp,
          const uint32_t* __restrict__ Wp, const float* __restrict__ bias,
          void* __restrict__ Cout, int n, int dout) {
    constexpr int DIN = K / 2;
    constexpr int SROW = DIN / 2;          // u32 per feature row per half
    constexpr int NCH = K / 32;
    constexpr int SA_ST = 20;              // u32 stride: 16 kpairs + 4 pad (conflict-free)
    constexpr int SB_ST = 136;             // u32 stride: 128 cols + 8 pad (conflict-free)
    constexpr int SA_ELEMS = 128 * SA_ST;  // 2560
    constexpr int SB_ELEMS = 16 * SB_ST;   // 2176
    extern __shared__ uint32_t smem[];
    uint32_t* sA[2] = { smem, smem + SA_ELEMS };
    uint32_t* sB[2] = { smem + 2 * SA_ELEMS, smem + 2 * SA_ELEMS + SB_ELEMS };
    const uint32_t sA32[2] = { smem_u32(sA[0]), smem_u32(sA[1]) };
    const uint32_t sB32[2] = { smem_u32(sB[0]), smem_u32(sB[1]) };

    const int tid  = threadIdx.x;
    const int lane = tid & 31, wid = tid >> 5;
    const int gid  = lane >> 2, tig = lane & 3;
    const int row0 = blockIdx.x * 128, col0 = blockIdx.y * 128;
    const int wr = wid & 3, wc = wid >> 2;

    auto issue = [&](int kc, int buf) {
        const int k0 = kc * 32;
        const uint32_t* base = (k0 < DIN) ? selfp : meanp;
        const int kp0 = ((k0 < DIN) ? k0 : (k0 - DIN)) >> 1;
        // A tile: 128 rows x 16 kpairs (64B/row = 4 x 16B)
#pragma unroll
        for (int it = 0; it < 2; it++) {
            int f = tid + it * 256;            // 0..511
            int r = f >> 2, seg = f & 3;
            bool ok = (row0 + r) < n;
            const uint32_t* g = base + (ok ? ((size_t)(row0 + r) * SROW + kp0 + seg * 4) : 0);
            cp_async16(sA32[buf] + (uint32_t)(r * SA_ST + seg * 4) * 4u, g, ok ? 16 : 0);
        }
        // B tile: 16 kpairs x 128 cols (512B/row = 32 x 16B)
        const int kpg = k0 >> 1;
#pragma unroll
        for (int it = 0; it < 2; it++) {
            int f = tid + it * 256;
            int kp = f >> 5, seg = f & 31;
            bool ok = (col0 + seg * 4) < DOUTP;
            const uint32_t* g = Wp + (ok ? ((size_t)(kpg + kp) * DOUTP + col0 + seg * 4) : 0);
            cp_async16(sB32[buf] + (uint32_t)(kp * SB_ST + seg * 4) * 4u, g, ok ? 16 : 0);
        }
        cp_commit();
    };

    float acc[2][8][4];
#pragma unroll
    for (int mi = 0; mi < 2; mi++)
#pragma unroll
        for (int ni = 0; ni < 8; ni++)
#pragma unroll
            for (int j = 0; j < 4; j++) acc[mi][ni][j] = 0.f;

    issue(0, 0);
    for (int kc = 0; kc < NCH; kc++) {
        const int buf = kc & 1;
        if (kc + 1 < NCH) { issue(kc + 1, buf ^ 1); cp_wait<1>(); }
        else              { cp_wait<0>(); }
        __syncthreads();
        const uint32_t* A_ = sA[buf];
        const uint32_t* B_ = sB[buf];
#pragma unroll
        for (int ks = 0; ks < 2; ks++) {           // two k16 steps per 32-chunk
            const int kb = ks * 8;                  // kpair base
            uint32_t a[2][4];
#pragma unroll
            for (int mi = 0; mi < 2; mi++) {
                int rb = wr * 32 + mi * 16;
                a[mi][0] = A_[(rb + gid)     * SA_ST + kb + tig];
                a[mi][1] = A_[(rb + gid + 8) * SA_ST + kb + tig];
                a[mi][2] = A_[(rb + gid)     * SA_ST + kb + tig + 4];
                a[mi][3] = A_[(rb + gid + 8) * SA_ST + kb + tig + 4];
            }
#pragma unroll
            for (int ni = 0; ni < 8; ni++) {
                int cb = wc * 64 + ni * 8 + gid;
                uint32_t b0 = B_[(kb + tig)     * SB_ST + cb];
                uint32_t b1 = B_[(kb + tig + 4) * SB_ST + cb];
#pragma unroll
                for (int mi = 0; mi < 2; mi++)
                    mma16n8k16(acc[mi][ni][0], acc[mi][ni][1], acc[mi][ni][2], acc[mi][ni][3],
                               a[mi][0], a[mi][1], a[mi][2], a[mi][3], b0, b1);
            }
        }
        __syncthreads();
    }

    // ---- epilogue ----
#pragma unroll
    for (int mi = 0; mi < 2; mi++) {
        int row = row0 + wr * 32 + mi * 16 + gid;
#pragma unroll
        for (int ni = 0; ni < 8; ni++) {
            int col = col0 + wc * 64 + ni * 8 + tig * 2;
#pragma unroll
            for (int half = 0; half < 2; half++) {
                int r = row + half * 8;
                if (r >= n) continue;
                float v0 = acc[mi][ni][half * 2 + 0];
                float v1 = acc[mi][ni][half * 2 + 1];
                if (FINAL) {
                    float* o = (float*)Cout;
                    if (col < dout)     o[(size_t)r * dout + col]     = v0 + __ldg(bias + col);
                    if (col + 1 < dout) o[(size_t)r * dout + col + 1] = v1 + __ldg(bias + col + 1);
                } else {
                    v0 = fmaxf(v0 + __ldg(bias + col), 0.f);
                    v1 = fmaxf(v1 + __ldg(bias + col + 1), 0.f);
                    ((uint32_t*)Cout)[(size_t)r * (DOUTP / 2) + (col >> 1)] = pack_h2(v0, v1);
                }
            }
        }
    }
}

// ---------------- host launcher ----------------
extern "C" void kernel_launch(void* const* d_in, const int* in_sizes, int n_in,
                              void* d_out, int out_size) {
    const float* x    = (const float*)d_in[0];
    const int*   src0 = (const int*)d_in[1];
    const int*   dst0 = (const int*)d_in[2];
    const int*   src1 = (const int*)d_in[3];
    const int*   dst1 = (const int*)d_in[4];
    const int*   src2 = (const int*)d_in[5];
    const int*   dst2 = (const int*)d_in[6];
    const float* Ws0  = (const float*)d_in[7];
    const float* Wn0  = (const float*)d_in[8];
    const float* b0   = (const float*)d_in[9];
    const float* Ws1  = (const float*)d_in[10];
    const float* Wn1  = (const float*)d_in[11];
    const float* b1   = (const float*)d_in[12];
    const float* Ws2  = (const float*)d_in[13];
    const float* Wn2  = (const float*)d_in[14];
    const float* b2   = (const float*)d_in[15];
    float* out = (float*)d_out;

    int E0 = in_sizes[1], E1 = in_sizes[3], E2 = in_sizes[5];
    int ET = E0 + E1 + E2;

    uint32_t *xr, *mean0, *h1, *mean1, *h2, *mean2, *Wp0, *Wp1, *Wp2;
    int *st0, *st1, *st2, *cn0, *cn1, *cn2, *ss0, *ss1, *ss2;
    cudaGetSymbolAddress((void**)&xr, g_xr);
    cudaGetSymbolAddress((void**)&mean0, g_mean0);
    cudaGetSymbolAddress((void**)&h1, g_h1);
    cudaGetSymbolAddress((void**)&mean1, g_mean1);
    cudaGetSymbolAddress((void**)&h2, g_h2);
    cudaGetSymbolAddress((void**)&mean2, g_mean2);
    cudaGetSymbolAddress((void**)&Wp0, g_Wp0);
    cudaGetSymbolAddress((void**)&Wp1, g_Wp1);
    cudaGetSymbolAddress((void**)&Wp2, g_Wp2);
    cudaGetSymbolAddress((void**)&st0, g_starts0);
    cudaGetSymbolAddress((void**)&st1, g_starts1);
    cudaGetSymbolAddress((void**)&st2, g_starts2);
    cudaGetSymbolAddress((void**)&cn0, g_cnt0);
    cudaGetSymbolAddress((void**)&cn1, g_cnt1);
    cudaGetSymbolAddress((void**)&cn2, g_cnt2);
    cudaGetSymbolAddress((void**)&ss0, g_ssrc0);
    cudaGetSymbolAddress((void**)&ss1, g_ssrc1);
    cudaGetSymbolAddress((void**)&ss2, g_ssrc2);

    // dynamic smem: 2*(128*20) + 2*(16*136) u32 = 37888 B
    const int SMEM = (2 * 128 * 20 + 2 * 16 * 136) * 4;
    cudaFuncSetAttribute(sage_gemm<256, 256, false>,
                         cudaFuncAttributeMaxDynamicSharedMemorySize, SMEM);
    cudaFuncSetAttribute(sage_gemm<512, 256, false>,
                         cudaFuncAttributeMaxDynamicSharedMemorySize, SMEM);
    cudaFuncSetAttribute(sage_gemm<512, 64, true>,
                         cudaFuncAttributeMaxDynamicSharedMemorySize, SMEM);

    // ---- sort pipeline + prep (serial; overlap regressed in R6) ----
    zero_counters<<<160, 256>>>();
    prep_kernel<<<592, 256>>>(x, Ws0, Wn0, Ws1, Wn1, Ws2, Wn2);
    hist_all<<<(ET + 255) / 256, 256>>>(dst0, E0, dst1, E1, dst2, E2);
    scan_block_all<<<NB0 + NB1 + NB2, 256>>>();
    scan_bsum_all<<<3, 512>>>();
    scan_add_all<<<NB0 + NB1 + NB2, 256>>>(E0, E1, E2);
    permute_all<<<(ET + 255) / 256, 256>>>(src0, dst0, E0, src1, dst1, E1, src2, dst2, E2);

    // ---- layer 0 ----
    agg0_kernel<<<(N1 * 32 + 255) / 256, 256>>>(x, ss0, st0, cn0, mean0);
    sage_gemm<256, 256, false><<<dim3((N1 + 127) / 128, 2), 256, SMEM>>>(
        xr, mean0, Wp0, b0, h1, N1, FH);

    // ---- layer 1 ----
    agg12_kernel<<<(N2 * 32 + 255) / 256, 256>>>(h1, ss1, st1, cn1, N2, mean1);
    sage_gemm<512, 256, false><<<dim3((N2 + 127) / 128, 2), 256, SMEM>>>(
        h1, mean1, Wp1, b1, h2, N2, FH);

    // ---- layer 2 ----
    agg12_kernel<<<(N3 * 32 + 255) / 256, 256>>>(h2, ss2, st2, cn2, N3, mean2);
    sage_gemm<512, 64, true><<<dim3((N3 + 127) / 128, 1), 256, SMEM>>>(
        h2, mean2, Wp2, b2, out, N3, FC);
}

// round 8
// speedup vs baseline: 1.8001x; 1.0882x over previous
#include <cuda_runtime.h>
#include <cuda_fp16.h>
#include <cstdint>

// ---------------- problem constants ----------------
#define N1 120000
#define N2 20000
#define N3 4000
#define E0C 1800000
#define E1C 200000
#define E2C 20000
#define FIN 128
#define FH  256
#define FC  47

// ---------------- device scratch (fp16 features packed as u32 = half2 along k) --------
__device__ uint32_t g_xr[(size_t)N1 * FIN / 2];
__device__ uint32_t g_mean0[(size_t)N1 * FIN / 2];
__device__ uint32_t g_h1[(size_t)N1 * FH / 2];
__device__ uint32_t g_mean1[(size_t)N2 * FH / 2];
__device__ uint32_t g_h2[(size_t)N2 * FH / 2];
__device__ uint32_t g_mean2[(size_t)N3 * FH / 2];
// weights transposed + packed: Wpt[n][kpair] = half2{W[2kp][n], W[2kp+1][n]}, [Ws;Wn]
__device__ uint32_t g_Wpt0[256 * 128];
__device__ uint32_t g_Wpt1[256 * 256];
__device__ uint32_t g_Wpt2[64 * 256];
// sort scratch
__device__ int g_cnt0[N1], g_starts0[N1 + 1], g_bsum0[512];
__device__ int g_cnt1[N2], g_starts1[N2 + 1], g_bsum1[512];
__device__ int g_cnt2[N3], g_starts2[N3 + 1], g_bsum2[512];
__device__ int g_ssrc0[E0C], g_ssrc1[E1C], g_ssrc2[E2C];

#define NB0 ((N1 + 255) / 256)
#define NB1 ((N2 + 255) / 256)
#define NB2 ((N3 + 255) / 256)

// ---------------- helpers ----------------
__device__ __forceinline__ uint32_t smem_u32(const void* p) {
    uint32_t a;
    asm("{ .reg .u64 t; cvta.to.shared.u64 t, %1; cvt.u32.u64 %0, t; }" : "=r"(a) : "l"(p));
    return a;
}
__device__ __forceinline__ void cp_async16(uint32_t saddr, const void* g, int sz) {
    asm volatile("cp.async.cg.shared.global [%0], [%1], 16, %2;"
                 :: "r"(saddr), "l"(g), "r"(sz) : "memory");
}
__device__ __forceinline__ void cp_commit() {
    asm volatile("cp.async.commit_group;" ::: "memory");
}
template <int N>
__device__ __forceinline__ void cp_wait() {
    asm volatile("cp.async.wait_group %0;" :: "n"(N) : "memory");
}
__device__ __forceinline__ uint32_t pack_h2(float lo, float hi) {
    __half2 h = __floats2half2_rn(lo, hi);
    return *(uint32_t*)&h;
}
__device__ __forceinline__ void ldm_x4(uint32_t* r, uint32_t addr) {
    asm volatile("ldmatrix.sync.aligned.m8n8.x4.shared.b16 {%0,%1,%2,%3}, [%4];"
                 : "=r"(r[0]), "=r"(r[1]), "=r"(r[2]), "=r"(r[3]) : "r"(addr));
}
__device__ __forceinline__ void mma16n8k16(float& c0, float& c1, float& c2, float& c3,
                                           uint32_t a0, uint32_t a1, uint32_t a2, uint32_t a3,
                                           uint32_t b0, uint32_t b1) {
    asm("mma.sync.aligned.m16n8k16.row.col.f32.f16.f16.f32 "
        "{%0,%1,%2,%3}, {%4,%5,%6,%7}, {%8,%9}, {%0,%1,%2,%3};"
        : "+f"(c0), "+f"(c1), "+f"(c2), "+f"(c3)
        : "r"(a0), "r"(a1), "r"(a2), "r"(a3), "r"(b0), "r"(b1));
}

// ---------------- prep: x[:N1] -> fp16, weights -> [n][kpair] fp16, zero counters ------
__global__ void prep_kernel(const float* __restrict__ x,
                            const float* __restrict__ Ws0, const float* __restrict__ Wn0,
                            const float* __restrict__ Ws1, const float* __restrict__ Wn1,
                            const float* __restrict__ Ws2, const float* __restrict__ Wn2) {
    int i0 = blockIdx.x * blockDim.x + threadIdx.x;
    int stride = gridDim.x * blockDim.x;
    for (int j = i0; j < N1; j += stride) g_cnt0[j] = 0;
    for (int j = i0; j < N2; j += stride) g_cnt1[j] = 0;
    for (int j = i0; j < N3; j += stride) g_cnt2[j] = 0;
    for (int i = i0; i < N1 * FIN / 2; i += stride) {
        float2 v = ((const float2*)x)[i];
        g_xr[i] = pack_h2(v.x, v.y);
    }
    // L0: 128 kpairs (64 self + 64 mean) x 256 n; coalesced reads over n
    for (int i = i0; i < 128 * 256; i += stride) {
        int kp = i >> 8, nn = i & 255;
        float lo, hi;
        if (kp < 64) { lo = Ws0[(2 * kp) * 256 + nn];       hi = Ws0[(2 * kp + 1) * 256 + nn]; }
        else { int q = kp - 64; lo = Wn0[(2 * q) * 256 + nn]; hi = Wn0[(2 * q + 1) * 256 + nn]; }
        g_Wpt0[nn * 128 + kp] = pack_h2(lo, hi);
    }
    // L1: 256 kpairs x 256 n
    for (int i = i0; i < 256 * 256; i += stride) {
        int kp = i >> 8, nn = i & 255;
        float lo, hi;
        if (kp < 128) { lo = Ws1[(2 * kp) * 256 + nn];       hi = Ws1[(2 * kp + 1) * 256 + nn]; }
        else { int q = kp - 128; lo = Wn1[(2 * q) * 256 + nn]; hi = Wn1[(2 * q + 1) * 256 + nn]; }
        g_Wpt1[nn * 256 + kp] = pack_h2(lo, hi);
    }
    // L2: 256 kpairs x 64 n (pad 47)
    for (int i = i0; i < 256 * 64; i += stride) {
        int kp = i >> 6, nn = i & 63;
        float lo = 0.f, hi = 0.f;
        if (nn < FC) {
            if (kp < 128) { lo = Ws2[(2 * kp) * FC + nn];       hi = Ws2[(2 * kp + 1) * FC + nn]; }
            else { int q = kp - 128; lo = Wn2[(2 * q) * FC + nn]; hi = Wn2[(2 * q + 1) * FC + nn]; }
        }
        g_Wpt2[nn * 256 + kp] = pack_h2(lo, hi);
    }
}

// ---------------- histogram ----------------
__global__ void hist_all(const int* __restrict__ d0, int nE0,
                         const int* __restrict__ d1, int nE1,
                         const int* __restrict__ d2, int nE2) {
    int i = blockIdx.x * blockDim.x + threadIdx.x;
    if (i < nE0)                    atomicAdd(&g_cnt0[__ldg(d0 + i)], 1);
    else if (i < nE0 + nE1)         atomicAdd(&g_cnt1[__ldg(d1 + i - nE0)], 1);
    else if (i < nE0 + nE1 + nE2)   atomicAdd(&g_cnt2[__ldg(d2 + i - nE0 - nE1)], 1);
}

// ---------------- fused scans ----------------
__global__ void scan_block_all() {
    __shared__ int s[256];
    int b = blockIdx.x;
    const int* cnt; int n, lb; int* starts; int* bsum;
    if (b < NB0)            { cnt = g_cnt0; n = N1; starts = g_starts0; bsum = g_bsum0; lb = b; }
    else if (b < NB0 + NB1) { cnt = g_cnt1; n = N2; starts = g_starts1; bsum = g_bsum1; lb = b - NB0; }
    else                    { cnt = g_cnt2; n = N3; starts = g_starts2; bsum = g_bsum2; lb = b - NB0 - NB1; }
    int i = lb * 256 + threadIdx.x;
    int v = (i < n) ? cnt[i] : 0;
    s[threadIdx.x] = v;
    __syncthreads();
    for (int off = 1; off < 256; off <<= 1) {
        int t = (threadIdx.x >= off) ? s[threadIdx.x - off] : 0;
        __syncthreads();
        s[threadIdx.x] += t;
        __syncthreads();
    }
    if (i < n) starts[i] = s[threadIdx.x] - v;
    if (threadIdx.x == 255) bsum[lb] = s[255];
}
__global__ void scan_bsum_all() {
    __shared__ int s[512];
    int* bsum; int nb;
    if (blockIdx.x == 0)      { bsum = g_bsum0; nb = NB0; }
    else if (blockIdx.x == 1) { bsum = g_bsum1; nb = NB1; }
    else                      { bsum = g_bsum2; nb = NB2; }
    int v = (threadIdx.x < nb) ? bsum[threadIdx.x] : 0;
    s[threadIdx.x] = v;
    __syncthreads();
    for (int off = 1; off < 512; off <<= 1) {
        int t = (threadIdx.x >= off) ? s[threadIdx.x - off] : 0;
        __syncthreads();
        s[threadIdx.x] += t;
        __syncthreads();
    }
    if (threadIdx.x < nb) bsum[threadIdx.x] = s[threadIdx.x] - v;
}
__global__ void scan_add_all(int nE0, int nE1, int nE2) {
    int b = blockIdx.x;
    int* starts; const int* bsum; int n, nE, lb;
    if (b < NB0)            { starts = g_starts0; bsum = g_bsum0; n = N1; nE = nE0; lb = b; }
    else if (b < NB0 + NB1) { starts = g_starts1; bsum = g_bsum1; n = N2; nE = nE1; lb = b - NB0; }
    else                    { starts = g_starts2; bsum = g_bsum2; n = N3; nE = nE2; lb = b - NB0 - NB1; }
    int i = lb * 256 + threadIdx.x;
    if (i < n) starts[i] += bsum[lb];
    if (lb == 0 && threadIdx.x == 0) starts[n] = nE;
}

// ---------------- permute (advances starts; agg recovers via cnt) ----------------
__global__ void permute_all(const int* __restrict__ s0, const int* __restrict__ d0, int nE0,
                            const int* __restrict__ s1, const int* __restrict__ d1, int nE1,
                            const int* __restrict__ s2, const int* __restrict__ d2, int nE2) {
    int i = blockIdx.x * blockDim.x + threadIdx.x;
    if (i < nE0) {
        int d = __ldg(d0 + i);
        g_ssrc0[atomicAdd(&g_starts0[d], 1)] = __ldg(s0 + i);
    } else if (i < nE0 + nE1) {
        int e = i - nE0, d = __ldg(d1 + e);
        g_ssrc1[atomicAdd(&g_starts1[d], 1)] = __ldg(s1 + e);
    } else if (i < nE0 + nE1 + nE2) {
        int e = i - nE0 - nE1, d = __ldg(d2 + e);
        g_ssrc2[atomicAdd(&g_starts2[d], 1)] = __ldg(s2 + e);
    }
}

// ---------------- agg layer0: fp32 gather -> fp16 mean ----------------
__global__ void agg0_kernel(const float* __restrict__ x, const int* __restrict__ ssrc,
                            const int* __restrict__ starts, const int* __restrict__ cnt,
                            uint32_t* __restrict__ mean) {
    int w = (int)((blockIdx.x * (unsigned)blockDim.x + threadIdx.x) >> 5);
    int lane = threadIdx.x & 31;
    if (w >= N1) return;
    int end = __ldg(starts + w), c = __ldg(cnt + w), beg = end - c;
    float4 acc = make_float4(0.f, 0.f, 0.f, 0.f);
    int i = beg;
    for (; i + 2 <= end; i += 2) {
        int s0 = __ldg(ssrc + i), s1 = __ldg(ssrc + i + 1);
        float4 a = __ldg((const float4*)(x + (size_t)s0 * FIN) + lane);
        float4 b = __ldg((const float4*)(x + (size_t)s1 * FIN) + lane);
        acc.x += a.x + b.x; acc.y += a.y + b.y; acc.z += a.z + b.z; acc.w += a.w + b.w;
    }
    if (i < end) {
        int s0 = __ldg(ssrc + i);
        float4 a = __ldg((const float4*)(x + (size_t)s0 * FIN) + lane);
        acc.x += a.x; acc.y += a.y; acc.z += a.z; acc.w += a.w;
    }
    float inv = (c > 0) ? (1.0f / (float)c) : 0.0f;
    uint2 o;
    o.x = pack_h2(acc.x * inv, acc.y * inv);
    o.y = pack_h2(acc.z * inv, acc.w * inv);
    *(uint2*)(mean + (size_t)w * (FIN / 2) + lane * 2) = o;
}

// ---------------- agg layers 1/2: fp16 gather -> fp16 mean ----------------
__global__ void agg12_kernel(const uint32_t* __restrict__ h, const int* __restrict__ ssrc,
                             const int* __restrict__ starts, const int* __restrict__ cnt,
                             int nD, uint32_t* __restrict__ mean) {
    int w = (int)((blockIdx.x * (unsigned)blockDim.x + threadIdx.x) >> 5);
    int lane = threadIdx.x & 31;
    if (w >= nD) return;
    int end = __ldg(starts + w), c = __ldg(cnt + w), beg = end - c;
    float acc[8];
#pragma unroll
    for (int j = 0; j < 8; j++) acc[j] = 0.f;
    int i = beg;
    for (; i + 2 <= end; i += 2) {
        int s0 = __ldg(ssrc + i), s1 = __ldg(ssrc + i + 1);
        uint4 a = __ldg((const uint4*)(h + (size_t)s0 * (FH / 2)) + lane);
        uint4 b = __ldg((const uint4*)(h + (size_t)s1 * (FH / 2)) + lane);
        const uint32_t av[4] = {a.x, a.y, a.z, a.w};
        const uint32_t bv[4] = {b.x, b.y, b.z, b.w};
#pragma unroll
        for (int j = 0; j < 4; j++) {
            float2 fa = __half22float2(*(const __half2*)&av[j]);
            float2 fb = __half22float2(*(const __half2*)&bv[j]);
            acc[2 * j] += fa.x + fb.x; acc[2 * j + 1] += fa.y + fb.y;
        }
    }
    if (i < end) {
        int s0 = __ldg(ssrc + i);
        uint4 a = __ldg((const uint4*)(h + (size_t)s0 * (FH / 2)) + lane);
        const uint32_t av[4] = {a.x, a.y, a.z, a.w};
#pragma unroll
        for (int j = 0; j < 4; j++) {
            float2 fa = __half22float2(*(const __half2*)&av[j]);
            acc[2 * j] += fa.x; acc[2 * j + 1] += fa.y;
        }
    }
    float inv = (c > 0) ? (1.0f / (float)c) : 0.0f;
    uint4 o;
    o.x = pack_h2(acc[0] * inv, acc[1] * inv);
    o.y = pack_h2(acc[2] * inv, acc[3] * inv);
    o.z = pack_h2(acc[4] * inv, acc[5] * inv);
    o.w = pack_h2(acc[6] * inv, acc[7] * inv);
    *((uint4*)(mean + (size_t)w * (FH / 2)) + lane) = o;
}

// ---------------- GEMM: cp.async + ldmatrix + m16n8k16 fp16 ----------------
// C[n, dout] = [self | mean] @ Wpt^T + bias. Both operands staged [row][kpair] u32,
// stride 36 (conflict-free ldmatrix). BM=128 x BN=128 x BK=64(kp32), 8 warps (32x64).
template <int K, int DOUTP, bool FINAL>
__global__ void __launch_bounds__(256, 2)
sage_gemm(const uint32_t* __restrict__ selfp, const uint32_t* __restrict__ meanp,
          const uint32_t* __restrict__ Wpt, const float* __restrict__ bias,
          void* __restrict__ Cout, int n, int dout) {
    constexpr int KP    = K / 2;     // total kpairs
    constexpr int DINKP = K / 4;     // kpairs per half
    constexpr int SROW  = K / 4;     // u32 per feature row (one half)
    constexpr int NCH   = KP / 32;   // 32-kpair chunks
    constexpr int ST    = 36;        // u32 stride (32 data + 4 pad)
    constexpr int TEL   = 128 * ST;  // 4608 u32 per tile
    extern __shared__ uint32_t smem[];
    uint32_t* sA[2] = { smem, smem + TEL };
    uint32_t* sB[2] = { smem + 2 * TEL, smem + 3 * TEL };
    const uint32_t sA32[2] = { smem_u32(sA[0]), smem_u32(sA[1]) };
    const uint32_t sB32[2] = { smem_u32(sB[0]), smem_u32(sB[1]) };

    const int tid  = threadIdx.x;
    const int lane = tid & 31, wid = tid >> 5;
    const int gid  = lane >> 2, tig = lane & 3;
    const int row0 = blockIdx.x * 128, col0 = blockIdx.y * 128;
    const int wr = wid & 3, wc = wid >> 2;

    // ldmatrix per-lane offsets (u32 units, within tile)
    const int aOff = (lane & 15) * ST + ((lane >> 4) << 2);
    const int bOff = ((lane & 7) | ((lane & 16) >> 1)) * ST + (((lane >> 3) & 1) << 2);

    auto issue = [&](int kc, int buf) {
        const int kp0 = kc * 32;
        const uint32_t* base = (kp0 < DINKP) ? selfp : meanp;
        const int kpl = (kp0 < DINKP) ? kp0 : (kp0 - DINKP);
#pragma unroll
        for (int it = 0; it < 4; it++) {                 // A: 128 rows x 8 segs
            int f = tid + it * 256;
            int r = f >> 3, seg = f & 7;
            bool ok = (row0 + r) < n;
            const uint32_t* g = base + (ok ? ((size_t)(row0 + r) * SROW + kpl + seg * 4) : 0);
            cp_async16(sA32[buf] + (uint32_t)(r * ST + seg * 4) * 4u, g, ok ? 16 : 0);
        }
#pragma unroll
        for (int it = 0; it < 4; it++) {                 // B: 128 n-rows x 8 segs
            int f = tid + it * 256;
            int r = f >> 3, seg = f & 7;
            bool ok = (col0 + r) < DOUTP;
            const uint32_t* g = Wpt + (ok ? ((size_t)(col0 + r) * KP + kp0 + seg * 4) : 0);
            cp_async16(sB32[buf] + (uint32_t)(r * ST + seg * 4) * 4u, g, ok ? 16 : 0);
        }
        cp_commit();
    };

    float acc[2][8][4];
#pragma unroll
    for (int mi = 0; mi < 2; mi++)
#pragma unroll
        for (int ni = 0; ni < 8; ni++)
#pragma unroll
            for (int j = 0; j < 4; j++) acc[mi][ni][j] = 0.f;

    issue(0, 0);
    for (int kc = 0; kc < NCH; kc++) {
        const int buf = kc & 1;
        if (kc + 1 < NCH) { issue(kc + 1, buf ^ 1); cp_wait<1>(); }
        else              { cp_wait<0>(); }
        __syncthreads();
        const uint32_t aBase = sA32[buf] + (uint32_t)(wr * 32 * ST + aOff) * 4u;
        const uint32_t bBase = sB32[buf] + (uint32_t)(wc * 64 * ST + bOff) * 4u;
#pragma unroll
        for (int ks = 0; ks < 4; ks++) {                 // 4 k16 steps per 32-kp chunk
            const uint32_t kbB = (uint32_t)(ks * 8) * 4u;
            uint32_t a[2][4];
#pragma unroll
            for (int mi = 0; mi < 2; mi++)
                ldm_x4(a[mi], aBase + (uint32_t)(mi * 16 * ST) * 4u + kbB);
#pragma unroll
            for (int nj = 0; nj < 4; nj++) {
                uint32_t b[4];
                ldm_x4(b, bBase + (uint32_t)(nj * 16 * ST) * 4u + kbB);
#pragma unroll
                for (int mi = 0; mi < 2; mi++) {
                    mma16n8k16(acc[mi][2 * nj][0], acc[mi][2 * nj][1],
                               acc[mi][2 * nj][2], acc[mi][2 * nj][3],
                               a[mi][0], a[mi][1], a[mi][2], a[mi][3], b[0], b[1]);
                    mma16n8k16(acc[mi][2 * nj + 1][0], acc[mi][2 * nj + 1][1],
                               acc[mi][2 * nj + 1][2], acc[mi][2 * nj + 1][3],
                               a[mi][0], a[mi][1], a[mi][2], a[mi][3], b[2], b[3]);
                }
            }
        }
        __syncthreads();
    }

    // ---- epilogue ----
#pragma unroll
    for (int mi = 0; mi < 2; mi++) {
        int row = row0 + wr * 32 + mi * 16 + gid;
#pragma unroll
        for (int ni = 0; ni < 8; ni++) {
            int col = col0 + wc * 64 + ni * 8 + tig * 2;
#pragma unroll
            for (int half = 0; half < 2; half++) {
                int r = row + half * 8;
                if (r >= n) continue;
                float v0 = acc[mi][ni][half * 2 + 0];
                float v1 = acc[mi][ni][half * 2 + 1];
                if (FINAL) {
                    float* o = (float*)Cout;
                    if (col < dout)     o[(size_t)r * dout + col]     = v0 + __ldg(bias + col);
                    if (col + 1 < dout) o[(size_t)r * dout + col + 1] = v1 + __ldg(bias + col + 1);
                } else {
                    v0 = fmaxf(v0 + __ldg(bias + col), 0.f);
                    v1 = fmaxf(v1 + __ldg(bias + col + 1), 0.f);
                    ((uint32_t*)Cout)[(size_t)r * (DOUTP / 2) + (col >> 1)] = pack_h2(v0, v1);
                }
            }
        }
    }
}

// ---------------- host launcher ----------------
extern "C" void kernel_launch(void* const* d_in, const int* in_sizes, int n_in,
                              void* d_out, int out_size) {
    const float* x    = (const float*)d_in[0];
    const int*   src0 = (const int*)d_in[1];
    const int*   dst0 = (const int*)d_in[2];
    const int*   src1 = (const int*)d_in[3];
    const int*   dst1 = (const int*)d_in[4];
    const int*   src2 = (const int*)d_in[5];
    const int*   dst2 = (const int*)d_in[6];
    const float* Ws0  = (const float*)d_in[7];
    const float* Wn0  = (const float*)d_in[8];
    const float* b0   = (const float*)d_in[9];
    const float* Ws1  = (const float*)d_in[10];
    const float* Wn1  = (const float*)d_in[11];
    const float* b1   = (const float*)d_in[12];
    const float* Ws2  = (const float*)d_in[13];
    const float* Wn2  = (const float*)d_in[14];
    const float* b2   = (const float*)d_in[15];
    float* out = (float*)d_out;

    int E0 = in_sizes[1], E1 = in_sizes[3], E2 = in_sizes[5];
    int ET = E0 + E1 + E2;

    uint32_t *xr, *mean0, *h1, *mean1, *h2, *mean2, *Wpt0, *Wpt1, *Wpt2;
    int *st0, *st1, *st2, *cn0, *cn1, *cn2, *ss0, *ss1, *ss2;
    cudaGetSymbolAddress((void**)&xr, g_xr);
    cudaGetSymbolAddress((void**)&mean0, g_mean0);
    cudaGetSymbolAddress((void**)&h1, g_h1);
    cudaGetSymbolAddress((void**)&mean1, g_mean1);
    cudaGetSymbolAddress((void**)&h2, g_h2);
    cudaGetSymbolAddress((void**)&mean2, g_mean2);
    cudaGetSymbolAddress((void**)&Wpt0, g_Wpt0);
    cudaGetSymbolAddress((void**)&Wpt1, g_Wpt1);
    cudaGetSymbolAddress((void**)&Wpt2, g_Wpt2);
    cudaGetSymbolAddress((void**)&st0, g_starts0);
    cudaGetSymbolAddress((void**)&st1, g_starts1);
    cudaGetSymbolAddress((void**)&st2, g_starts2);
    cudaGetSymbolAddress((void**)&cn0, g_cnt0);
    cudaGetSymbolAddress((void**)&cn1, g_cnt1);
    cudaGetSymbolAddress((void**)&cn2, g_cnt2);
    cudaGetSymbolAddress((void**)&ss0, g_ssrc0);
    cudaGetSymbolAddress((void**)&ss1, g_ssrc1);
    cudaGetSymbolAddress((void**)&ss2, g_ssrc2);

    // dynamic smem: 4 tiles x 128*36 u32 = 73728 B
    const int SMEM = 4 * 128 * 36 * 4;
    cudaFuncSetAttribute(sage_gemm<256, 256, false>,
                         cudaFuncAttributeMaxDynamicSharedMemorySize, SMEM);
    cudaFuncSetAttribute(sage_gemm<512, 256, false>,
                         cudaFuncAttributeMaxDynamicSharedMemorySize, SMEM);
    cudaFuncSetAttribute(sage_gemm<512, 64, true>,
                         cudaFuncAttributeMaxDynamicSharedMemorySize, SMEM);

    // ---- prep (incl. counter zeroing) + sort pipeline ----
    prep_kernel<<<592, 256>>>(x, Ws0, Wn0, Ws1, Wn1, Ws2, Wn2);
    hist_all<<<(ET + 255) / 256, 256>>>(dst0, E0, dst1, E1, dst2, E2);
    scan_block_all<<<NB0 + NB1 + NB2, 256>>>();
    scan_bsum_all<<<3, 512>>>();
    scan_add_all<<<NB0 + NB1 + NB2, 256>>>(E0, E1, E2);
    permute_all<<<(ET + 255) / 256, 256>>>(src0, dst0, E0, src1, dst1, E1, src2, dst2, E2);

    // ---- layer 0 ----
    agg0_kernel<<<(N1 * 32 + 255) / 256, 256>>>(x, ss0, st0, cn0, mean0);
    sage_gemm<256, 256, false><<<dim3((N1 + 127) / 128, 2), 256, SMEM>>>(
        xr, mean0, Wpt0, b0, h1, N1, FH);

    // ---- layer 1 ----
    agg12_kernel<<<(N2 * 32 + 255) / 256, 256>>>(h1, ss1, st1, cn1, N2, mean1);
    sage_gemm<512, 256, false><<<dim3((N2 + 127) / 128, 2), 256, SMEM>>>(
        h1, mean1, Wpt1, b1, h2, N2, FH);

    // ---- layer 2 ----
    agg12_kernel<<<(N3 * 32 + 255) / 256, 256>>>(h2, ss2, st2, cn2, N3, mean2);
    sage_gemm<512, 64, true><<<dim3((N3 + 127) / 128, 1), 256, SMEM>>>(
        h2, mean2, Wpt2, b2, out, N3, FC);
}

// round 9
// speedup vs baseline: 1.8592x; 1.0328x over previous
#include <cuda_runtime.h>
#include <cuda_fp16.h>
#include <cstdint>

// ---------------- problem constants ----------------
#define N0 400000
#define N1 120000
#define N2 20000
#define N3 4000
#define E0C 1800000
#define E1C 200000
#define E2C 20000
#define FIN 128
#define FH  256
#define FC  47

// ---------------- device scratch (fp16 features packed as u32 = half2 along k) --------
__device__ uint32_t g_xh[(size_t)N0 * FIN / 2];      // ALL of x in fp16 (102 MB, L2-friendly)
__device__ uint32_t g_mean0[(size_t)N1 * FIN / 2];
__device__ uint32_t g_h1[(size_t)N1 * FH / 2];
__device__ uint32_t g_mean1[(size_t)N2 * FH / 2];
__device__ uint32_t g_h2[(size_t)N2 * FH / 2];
__device__ uint32_t g_mean2[(size_t)N3 * FH / 2];
// weights transposed + packed: Wpt[n][kpair] = half2{W[2kp][n], W[2kp+1][n]}, [Ws;Wn]
__device__ uint32_t g_Wpt0[256 * 128];
__device__ uint32_t g_Wpt1[256 * 256];
__device__ uint32_t g_Wpt2[64 * 256];
// sort scratch
__device__ int g_cnt0[N1], g_starts0[N1 + 1], g_bsum0[512];
__device__ int g_cnt1[N2], g_starts1[N2 + 1], g_bsum1[512];
__device__ int g_cnt2[N3], g_starts2[N3 + 1], g_bsum2[512];
__device__ int g_ssrc0[E0C], g_ssrc1[E1C], g_ssrc2[E2C];

#define NB0 ((N1 + 255) / 256)
#define NB1 ((N2 + 255) / 256)
#define NB2 ((N3 + 255) / 256)

// ---------------- helpers ----------------
__device__ __forceinline__ uint32_t smem_u32(const void* p) {
    uint32_t a;
    asm("{ .reg .u64 t; cvta.to.shared.u64 t, %1; cvt.u32.u64 %0, t; }" : "=r"(a) : "l"(p));
    return a;
}
__device__ __forceinline__ void cp_async16(uint32_t saddr, const void* g, int sz) {
    asm volatile("cp.async.cg.shared.global [%0], [%1], 16, %2;"
                 :: "r"(saddr), "l"(g), "r"(sz) : "memory");
}
__device__ __forceinline__ void cp_commit() {
    asm volatile("cp.async.commit_group;" ::: "memory");
}
template <int N>
__device__ __forceinline__ void cp_wait() {
    asm volatile("cp.async.wait_group %0;" :: "n"(N) : "memory");
}
__device__ __forceinline__ uint32_t pack_h2(float lo, float hi) {
    __half2 h = __floats2half2_rn(lo, hi);
    return *(uint32_t*)&h;
}
__device__ __forceinline__ void acc_h2(float& lo, float& hi, uint32_t u) {
    float2 f = __half22float2(*(const __half2*)&u);
    lo += f.x; hi += f.y;
}
__device__ __forceinline__ void ldm_x4(uint32_t* r, uint32_t addr) {
    asm volatile("ldmatrix.sync.aligned.m8n8.x4.shared.b16 {%0,%1,%2,%3}, [%4];"
                 : "=r"(r[0]), "=r"(r[1]), "=r"(r[2]), "=r"(r[3]) : "r"(addr));
}
__device__ __forceinline__ void mma16n8k16(float& c0, float& c1, float& c2, float& c3,
                                           uint32_t a0, uint32_t a1, uint32_t a2, uint32_t a3,
                                           uint32_t b0, uint32_t b1) {
    asm("mma.sync.aligned.m16n8k16.row.col.f32.f16.f16.f32 "
        "{%0,%1,%2,%3}, {%4,%5,%6,%7}, {%8,%9}, {%0,%1,%2,%3};"
        : "+f"(c0), "+f"(c1), "+f"(c2), "+f"(c3)
        : "r"(a0), "r"(a1), "r"(a2), "r"(a3), "r"(b0), "r"(b1));
}

// ---------------- prep: ALL x -> fp16, weights -> [n][kpair] fp16, zero counters ------
__global__ void prep_kernel(const float* __restrict__ x,
                            const float* __restrict__ Ws0, const float* __restrict__ Wn0,
                            const float* __restrict__ Ws1, const float* __restrict__ Wn1,
                            const float* __restrict__ Ws2, const float* __restrict__ Wn2) {
    int i0 = blockIdx.x * blockDim.x + threadIdx.x;
    int stride = gridDim.x * blockDim.x;
    for (int j = i0; j < N1; j += stride) g_cnt0[j] = 0;
    for (int j = i0; j < N2; j += stride) g_cnt1[j] = 0;
    for (int j = i0; j < N3; j += stride) g_cnt2[j] = 0;
    for (size_t i = i0; i < (size_t)N0 * FIN / 2; i += stride) {
        float2 v = ((const float2*)x)[i];
        g_xh[i] = pack_h2(v.x, v.y);
    }
    for (int i = i0; i < 128 * 256; i += stride) {       // L0: 128 kpairs x 256 n
        int kp = i >> 8, nn = i & 255;
        float lo, hi;
        if (kp < 64) { lo = Ws0[(2 * kp) * 256 + nn];       hi = Ws0[(2 * kp + 1) * 256 + nn]; }
        else { int q = kp - 64; lo = Wn0[(2 * q) * 256 + nn]; hi = Wn0[(2 * q + 1) * 256 + nn]; }
        g_Wpt0[nn * 128 + kp] = pack_h2(lo, hi);
    }
    for (int i = i0; i < 256 * 256; i += stride) {       // L1: 256 kpairs x 256 n
        int kp = i >> 8, nn = i & 255;
        float lo, hi;
        if (kp < 128) { lo = Ws1[(2 * kp) * 256 + nn];       hi = Ws1[(2 * kp + 1) * 256 + nn]; }
        else { int q = kp - 128; lo = Wn1[(2 * q) * 256 + nn]; hi = Wn1[(2 * q + 1) * 256 + nn]; }
        g_Wpt1[nn * 256 + kp] = pack_h2(lo, hi);
    }
    for (int i = i0; i < 256 * 64; i += stride) {        // L2: 256 kpairs x 64 n (pad 47)
        int kp = i >> 6, nn = i & 63;
        float lo = 0.f, hi = 0.f;
        if (nn < FC) {
            if (kp < 128) { lo = Ws2[(2 * kp) * FC + nn];       hi = Ws2[(2 * kp + 1) * FC + nn]; }
            else { int q = kp - 128; lo = Wn2[(2 * q) * FC + nn]; hi = Wn2[(2 * q + 1) * FC + nn]; }
        }
        g_Wpt2[nn * 256 + kp] = pack_h2(lo, hi);
    }
}

// ---------------- histogram ----------------
__global__ void hist_all(const int* __restrict__ d0, int nE0,
                         const int* __restrict__ d1, int nE1,
                         const int* __restrict__ d2, int nE2) {
    int i = blockIdx.x * blockDim.x + threadIdx.x;
    if (i < nE0)                    atomicAdd(&g_cnt0[__ldg(d0 + i)], 1);
    else if (i < nE0 + nE1)         atomicAdd(&g_cnt1[__ldg(d1 + i - nE0)], 1);
    else if (i < nE0 + nE1 + nE2)   atomicAdd(&g_cnt2[__ldg(d2 + i - nE0 - nE1)], 1);
}

// ---------------- fused scans ----------------
__global__ void scan_block_all() {
    __shared__ int s[256];
    int b = blockIdx.x;
    const int* cnt; int n, lb; int* starts; int* bsum;
    if (b < NB0)            { cnt = g_cnt0; n = N1; starts = g_starts0; bsum = g_bsum0; lb = b; }
    else if (b < NB0 + NB1) { cnt = g_cnt1; n = N2; starts = g_starts1; bsum = g_bsum1; lb = b - NB0; }
    else                    { cnt = g_cnt2; n = N3; starts = g_starts2; bsum = g_bsum2; lb = b - NB0 - NB1; }
    int i = lb * 256 + threadIdx.x;
    int v = (i < n) ? cnt[i] : 0;
    s[threadIdx.x] = v;
    __syncthreads();
    for (int off = 1; off < 256; off <<= 1) {
        int t = (threadIdx.x >= off) ? s[threadIdx.x - off] : 0;
        __syncthreads();
        s[threadIdx.x] += t;
        __syncthreads();
    }
    if (i < n) starts[i] = s[threadIdx.x] - v;
    if (threadIdx.x == 255) bsum[lb] = s[255];
}
__global__ void scan_bsum_all() {
    __shared__ int s[512];
    int* bsum; int nb;
    if (blockIdx.x == 0)      { bsum = g_bsum0; nb = NB0; }
    else if (blockIdx.x == 1) { bsum = g_bsum1; nb = NB1; }
    else                      { bsum = g_bsum2; nb = NB2; }
    int v = (threadIdx.x < nb) ? bsum[threadIdx.x] : 0;
    s[threadIdx.x] = v;
    __syncthreads();
    for (int off = 1; off < 512; off <<= 1) {
        int t = (threadIdx.x >= off) ? s[threadIdx.x - off] : 0;
        __syncthreads();
        s[threadIdx.x] += t;
        __syncthreads();
    }
    if (threadIdx.x < nb) bsum[threadIdx.x] = s[threadIdx.x] - v;
}
__global__ void scan_add_all(int nE0, int nE1, int nE2) {
    int b = blockIdx.x;
    int* starts; const int* bsum; int n, nE, lb;
    if (b < NB0)            { starts = g_starts0; bsum = g_bsum0; n = N1; nE = nE0; lb = b; }
    else if (b < NB0 + NB1) { starts = g_starts1; bsum = g_bsum1; n = N2; nE = nE1; lb = b - NB0; }
    else                    { starts = g_starts2; bsum = g_bsum2; n = N3; nE = nE2; lb = b - NB0 - NB1; }
    int i = lb * 256 + threadIdx.x;
    if (i < n) starts[i] += bsum[lb];
    if (lb == 0 && threadIdx.x == 0) starts[n] = nE;
}

// ---------------- permute (advances starts; agg recovers via cnt) ----------------
__global__ void permute_all(const int* __restrict__ s0, const int* __restrict__ d0, int nE0,
                            const int* __restrict__ s1, const int* __restrict__ d1, int nE1,
                            const int* __restrict__ s2, const int* __restrict__ d2, int nE2) {
    int i = blockIdx.x * blockDim.x + threadIdx.x;
    if (i < nE0) {
        int d = __ldg(d0 + i);
        g_ssrc0[atomicAdd(&g_starts0[d], 1)] = __ldg(s0 + i);
    } else if (i < nE0 + nE1) {
        int e = i - nE0, d = __ldg(d1 + e);
        g_ssrc1[atomicAdd(&g_starts1[d], 1)] = __ldg(s1 + e);
    } else if (i < nE0 + nE1 + nE2) {
        int e = i - nE0 - nE1, d = __ldg(d2 + e);
        g_ssrc2[atomicAdd(&g_starts2[d], 1)] = __ldg(s2 + e);
    }
}

// ---------------- agg layer0: fp16 gather (L2-resident) -> fp16 mean, DIN=128 ---------
__global__ void agg0_kernel(const uint32_t* __restrict__ xh, const int* __restrict__ ssrc,
                            const int* __restrict__ starts, const int* __restrict__ cnt,
                            uint32_t* __restrict__ mean) {
    constexpr int RW = FIN / 2;    // 64 u32 per row
    int w = (int)((blockIdx.x * (unsigned)blockDim.x + threadIdx.x) >> 5);
    int lane = threadIdx.x & 31;
    if (w >= N1) return;
    int end = __ldg(starts + w), c = __ldg(cnt + w), beg = end - c;
    float4 acc = make_float4(0.f, 0.f, 0.f, 0.f);   // 4 halves per lane (2 u32)
    int i = beg;
    for (; i + 4 <= end; i += 4) {
        int s0 = __ldg(ssrc + i),     s1 = __ldg(ssrc + i + 1);
        int s2 = __ldg(ssrc + i + 2), s3 = __ldg(ssrc + i + 3);
        uint2 a = __ldg((const uint2*)(xh + (size_t)s0 * RW) + lane);
        uint2 b = __ldg((const uint2*)(xh + (size_t)s1 * RW) + lane);
        uint2 cc = __ldg((const uint2*)(xh + (size_t)s2 * RW) + lane);
        uint2 d = __ldg((const uint2*)(xh + (size_t)s3 * RW) + lane);
        acc_h2(acc.x, acc.y, a.x);  acc_h2(acc.z, acc.w, a.y);
        acc_h2(acc.x, acc.y, b.x);  acc_h2(acc.z, acc.w, b.y);
        acc_h2(acc.x, acc.y, cc.x); acc_h2(acc.z, acc.w, cc.y);
        acc_h2(acc.x, acc.y, d.x);  acc_h2(acc.z, acc.w, d.y);
    }
    for (; i < end; i++) {
        int s0 = __ldg(ssrc + i);
        uint2 a = __ldg((const uint2*)(xh + (size_t)s0 * RW) + lane);
        acc_h2(acc.x, acc.y, a.x);  acc_h2(acc.z, acc.w, a.y);
    }
    float inv = (c > 0) ? (1.0f / (float)c) : 0.0f;
    uint2 o;
    o.x = pack_h2(acc.x * inv, acc.y * inv);
    o.y = pack_h2(acc.z * inv, acc.w * inv);
    *((uint2*)(mean + (size_t)w * RW) + lane) = o;
}

// ---------------- agg layers 1/2: fp16 gather -> fp16 mean, DIN=256 -------------------
__global__ void agg12_kernel(const uint32_t* __restrict__ h, const int* __restrict__ ssrc,
                             const int* __restrict__ starts, const int* __restrict__ cnt,
                             int nD, uint32_t* __restrict__ mean) {
    int w = (int)((blockIdx.x * (unsigned)blockDim.x + threadIdx.x) >> 5);
    int lane = threadIdx.x & 31;
    if (w >= nD) return;
    int end = __ldg(starts + w), c = __ldg(cnt + w), beg = end - c;
    float acc[8];
#pragma unroll
    for (int j = 0; j < 8; j++) acc[j] = 0.f;
    int i = beg;
    for (; i + 2 <= end; i += 2) {
        int s0 = __ldg(ssrc + i), s1 = __ldg(ssrc + i + 1);
        uint4 a = __ldg((const uint4*)(h + (size_t)s0 * (FH / 2)) + lane);
        uint4 b = __ldg((const uint4*)(h + (size_t)s1 * (FH / 2)) + lane);
        acc_h2(acc[0], acc[1], a.x); acc_h2(acc[2], acc[3], a.y);
        acc_h2(acc[4], acc[5], a.z); acc_h2(acc[6], acc[7], a.w);
        acc_h2(acc[0], acc[1], b.x); acc_h2(acc[2], acc[3], b.y);
        acc_h2(acc[4], acc[5], b.z); acc_h2(acc[6], acc[7], b.w);
    }
    if (i < end) {
        int s0 = __ldg(ssrc + i);
        uint4 a = __ldg((const uint4*)(h + (size_t)s0 * (FH / 2)) + lane);
        acc_h2(acc[0], acc[1], a.x); acc_h2(acc[2], acc[3], a.y);
        acc_h2(acc[4], acc[5], a.z); acc_h2(acc[6], acc[7], a.w);
    }
    float inv = (c > 0) ? (1.0f / (float)c) : 0.0f;
    uint4 o;
    o.x = pack_h2(acc[0] * inv, acc[1] * inv);
    o.y = pack_h2(acc[2] * inv, acc[3] * inv);
    o.z = pack_h2(acc[4] * inv, acc[5] * inv);
    o.w = pack_h2(acc[6] * inv, acc[7] * inv);
    *((uint4*)(mean + (size_t)w * (FH / 2)) + lane) = o;
}

// ---------------- GEMM: cp.async + ldmatrix + m16n8k16 fp16 ----------------
template <int K, int DOUTP, bool FINAL>
__global__ void __launch_bounds__(256, 2)
sage_gemm(const uint32_t* __restrict__ selfp, const uint32_t* __restrict__ meanp,
          const uint32_t* __restrict__ Wpt, const float* __restrict__ bias,
          void* __restrict__ Cout, int n, int dout) {
    constexpr int KP    = K / 2;
    constexpr int DINKP = K / 4;
    constexpr int SROW  = K / 4;
    constexpr int NCH   = KP / 32;
    constexpr int ST    = 36;
    constexpr int TEL   = 128 * ST;
    extern __shared__ uint32_t smem[];
    uint32_t* sA[2] = { smem, smem + TEL };
    uint32_t* sB[2] = { smem + 2 * TEL, smem + 3 * TEL };
    const uint32_t sA32[2] = { smem_u32(sA[0]), smem_u32(sA[1]) };
    const uint32_t sB32[2] = { smem_u32(sB[0]), smem_u32(sB[1]) };

    const int tid  = threadIdx.x;
    const int lane = tid & 31, wid = tid >> 5;
    const int gid  = lane >> 2, tig = lane & 3;
    const int row0 = blockIdx.x * 128, col0 = blockIdx.y * 128;
    const int wr = wid & 3, wc = wid >> 2;

    const int aOff = (lane & 15) * ST + ((lane >> 4) << 2);
    const int bOff = ((lane & 7) | ((lane & 16) >> 1)) * ST + (((lane >> 3) & 1) << 2);

    auto issue = [&](int kc, int buf) {
        const int kp0 = kc * 32;
        const uint32_t* base = (kp0 < DINKP) ? selfp : meanp;
        const int kpl = (kp0 < DINKP) ? kp0 : (kp0 - DINKP);
#pragma unroll
        for (int it = 0; it < 4; it++) {
            int f = tid + it * 256;
            int r = f >> 3, seg = f & 7;
            bool ok = (row0 + r) < n;
            const uint32_t* g = base + (ok ? ((size_t)(row0 + r) * SROW + kpl + seg * 4) : 0);
            cp_async16(sA32[buf] + (uint32_t)(r * ST + seg * 4) * 4u, g, ok ? 16 : 0);
        }
#pragma unroll
        for (int it = 0; it < 4; it++) {
            int f = tid + it * 256;
            int r = f >> 3, seg = f & 7;
            bool ok = (col0 + r) < DOUTP;
            const uint32_t* g = Wpt + (ok ? ((size_t)(col0 + r) * KP + kp0 + seg * 4) : 0);
            cp_async16(sB32[buf] + (uint32_t)(r * ST + seg * 4) * 4u, g, ok ? 16 : 0);
        }
        cp_commit();
    };

    float acc[2][8][4];
#pragma unroll
    for (int mi = 0; mi < 2; mi++)
#pragma unroll
        for (int ni = 0; ni < 8; ni++)
#pragma unroll
            for (int j = 0; j < 4; j++) acc[mi][ni][j] = 0.f;

    issue(0, 0);
    for (int kc = 0; kc < NCH; kc++) {
        const int buf = kc & 1;
        if (kc + 1 < NCH) { issue(kc + 1, buf ^ 1); cp_wait<1>(); }
        else              { cp_wait<0>(); }
        __syncthreads();
        const uint32_t aBase = sA32[buf] + (uint32_t)(wr * 32 * ST + aOff) * 4u;
        const uint32_t bBase = sB32[buf] + (uint32_t)(wc * 64 * ST + bOff) * 4u;
#pragma unroll
        for (int ks = 0; ks < 4; ks++) {
            const uint32_t kbB = (uint32_t)(ks * 8) * 4u;
            uint32_t a[2][4];
#pragma unroll
            for (int mi = 0; mi < 2; mi++)
                ldm_x4(a[mi], aBase + (uint32_t)(mi * 16 * ST) * 4u + kbB);
#pragma unroll
            for (int nj = 0; nj < 4; nj++) {
                uint32_t b[4];
                ldm_x4(b, bBase + (uint32_t)(nj * 16 * ST) * 4u + kbB);
#pragma unroll
                for (int mi = 0; mi < 2; mi++) {
                    mma16n8k16(acc[mi][2 * nj][0], acc[mi][2 * nj][1],
                               acc[mi][2 * nj][2], acc[mi][2 * nj][3],
                               a[mi][0], a[mi][1], a[mi][2], a[mi][3], b[0], b[1]);
                    mma16n8k16(acc[mi][2 * nj + 1][0], acc[mi][2 * nj + 1][1],
                               acc[mi][2 * nj + 1][2], acc[mi][2 * nj + 1][3],
                               a[mi][0], a[mi][1], a[mi][2], a[mi][3], b[2], b[3]);
                }
            }
        }
        __syncthreads();
    }

#pragma unroll
    for (int mi = 0; mi < 2; mi++) {
        int row = row0 + wr * 32 + mi * 16 + gid;
#pragma unroll
        for (int ni = 0; ni < 8; ni++) {
            int col = col0 + wc * 64 + ni * 8 + tig * 2;
#pragma unroll
            for (int half = 0; half < 2; half++) {
                int r = row + half * 8;
                if (r >= n) continue;
                float v0 = acc[mi][ni][half * 2 + 0];
                float v1 = acc[mi][ni][half * 2 + 1];
                if (FINAL) {
                    float* o = (float*)Cout;
                    if (col < dout)     o[(size_t)r * dout + col]     = v0 + __ldg(bias + col);
                    if (col + 1 < dout) o[(size_t)r * dout + col + 1] = v1 + __ldg(bias + col + 1);
                } else {
                    v0 = fmaxf(v0 + __ldg(bias + col), 0.f);
                    v1 = fmaxf(v1 + __ldg(bias + col + 1), 0.f);
                    ((uint32_t*)Cout)[(size_t)r * (DOUTP / 2) + (col >> 1)] = pack_h2(v0, v1);
                }
            }
        }
    }
}

// ---------------- host launcher ----------------
extern "C" void kernel_launch(void* const* d_in, const int* in_sizes, int n_in,
                              void* d_out, int out_size) {
    const float* x    = (const float*)d_in[0];
    const int*   src0 = (const int*)d_in[1];
    const int*   dst0 = (const int*)d_in[2];
    const int*   src1 = (const int*)d_in[3];
    const int*   dst1 = (const int*)d_in[4];
    const int*   src2 = (const int*)d_in[5];
    const int*   dst2 = (const int*)d_in[6];
    const float* Ws0  = (const float*)d_in[7];
    const float* Wn0  = (const float*)d_in[8];
    const float* b0   = (const float*)d_in[9];
    const float* Ws1  = (const float*)d_in[10];
    const float* Wn1  = (const float*)d_in[11];
    const float* b1   = (const float*)d_in[12];
    const float* Ws2  = (const float*)d_in[13];
    const float* Wn2  = (const float*)d_in[14];
    const float* b2   = (const float*)d_in[15];
    float* out = (float*)d_out;

    int E0 = in_sizes[1], E1 = in_sizes[3], E2 = in_sizes[5];
    int ET = E0 + E1 + E2;

    uint32_t *xh, *mean0, *h1, *mean1, *h2, *mean2, *Wpt0, *Wpt1, *Wpt2;
    int *st0, *st1, *st2, *cn0, *cn1, *cn2, *ss0, *ss1, *ss2;
    cudaGetSymbolAddress((void**)&xh, g_xh);
    cudaGetSymbolAddress((void**)&mean0, g_mean0);
    cudaGetSymbolAddress((void**)&h1, g_h1);
    cudaGetSymbolAddress((void**)&mean1, g_mean1);
    cudaGetSymbolAddress((void**)&h2, g_h2);
    cudaGetSymbolAddress((void**)&mean2, g_mean2);
    cudaGetSymbolAddress((void**)&Wpt0, g_Wpt0);
    cudaGetSymbolAddress((void**)&Wpt1, g_Wpt1);
    cudaGetSymbolAddress((void**)&Wpt2, g_Wpt2);
    cudaGetSymbolAddress((void**)&st0, g_starts0);
    cudaGetSymbolAddress((void**)&st1, g_starts1);
    cudaGetSymbolAddress((void**)&st2, g_starts2);
    cudaGetSymbolAddress((void**)&cn0, g_cnt0);
    cudaGetSymbolAddress((void**)&cn1, g_cnt1);
    cudaGetSymbolAddress((void**)&cn2, g_cnt2);
    cudaGetSymbolAddress((void**)&ss0, g_ssrc0);
    cudaGetSymbolAddress((void**)&ss1, g_ssrc1);
    cudaGetSymbolAddress((void**)&ss2, g_ssrc2);

    const int SMEM = 4 * 128 * 36 * 4;   // 73728 B
    cudaFuncSetAttribute(sage_gemm<256, 256, false>,
                         cudaFuncAttributeMaxDynamicSharedMemorySize, SMEM);
    cudaFuncSetAttribute(sage_gemm<512, 256, false>,
                         cudaFuncAttributeMaxDynamicSharedMemorySize, SMEM);
    cudaFuncSetAttribute(sage_gemm<512, 64, true>,
                         cudaFuncAttributeMaxDynamicSharedMemorySize, SMEM);

    // ---- prep (zero + convert + weights) + sort pipeline ----
    prep_kernel<<<1184, 256>>>(x, Ws0, Wn0, Ws1, Wn1, Ws2, Wn2);
    hist_all<<<(ET + 255) / 256, 256>>>(dst0, E0, dst1, E1, dst2, E2);
    scan_block_all<<<NB0 + NB1 + NB2, 256>>>();
    scan_bsum_all<<<3, 512>>>();
    scan_add_all<<<NB0 + NB1 + NB2, 256>>>(E0, E1, E2);
    permute_all<<<(ET + 255) / 256, 256>>>(src0, dst0, E0, src1, dst1, E1, src2, dst2, E2);

    // ---- layer 0 ----
    agg0_kernel<<<(N1 * 32 + 255) / 256, 256>>>(xh, ss0, st0, cn0, mean0);
    sage_gemm<256, 256, false><<<dim3((N1 + 127) / 128, 2), 256, SMEM>>>(
        xh, mean0, Wpt0, b0, h1, N1, FH);

    // ---- layer 1 ----
    agg12_kernel<<<(N2 * 32 + 255) / 256, 256>>>(h1, ss1, st1, cn1, N2, mean1);
    sage_gemm<512, 256, false><<<dim3((N2 + 127) / 128, 2), 256, SMEM>>>(
        h1, mean1, Wpt1, b1, h2, N2, FH);

    // ---- layer 2 ----
    agg12_kernel<<<(N3 * 32 + 255) / 256, 256>>>(h2, ss2, st2, cn2, N3, mean2);
    sage_gemm<512, 64, true><<<dim3((N3 + 127) / 128, 1), 256, SMEM>>>(
        h2, mean2, Wpt2, b2, out, N3, FC);
}

// round 10
// speedup vs baseline: 1.8996x; 1.0218x over previous
#include <cuda_runtime.h>
#include <cuda_fp16.h>
#include <cstdint>

// ---------------- problem constants ----------------
#define N0 400000
#define N1 120000
#define N2 20000
#define N3 4000
#define E0C 1800000
#define E1C 200000
#define E2C 20000
#define FIN 128
#define FH  256
#define FC  47

// ---------------- device scratch (fp16 features packed as u32 = half2 along k) --------
__device__ uint32_t g_xh[(size_t)N0 * FIN / 2];      // ALL of x in fp16
__device__ uint32_t g_mean0[(size_t)N1 * FIN / 2];
__device__ uint32_t g_h1[(size_t)N1 * FH / 2];
__device__ uint32_t g_mean1[(size_t)N2 * FH / 2];
__device__ uint32_t g_h2[(size_t)N2 * FH / 2];
__device__ uint32_t g_mean2[(size_t)N3 * FH / 2];
// weights transposed + packed: Wpt[n][kpair] = half2{W[2kp][n], W[2kp+1][n]}, [Ws;Wn]
__device__ uint32_t g_Wpt0[256 * 128];
__device__ uint32_t g_Wpt1[256 * 256];
__device__ uint32_t g_Wpt2[64 * 256];
// sort scratch
__device__ int g_cnt0[N1], g_starts0[N1 + 1], g_bsum0[512];
__device__ int g_cnt1[N2], g_starts1[N2 + 1], g_bsum1[512];
__device__ int g_cnt2[N3], g_starts2[N3 + 1], g_bsum2[512];
__device__ int g_ssrc0[E0C], g_ssrc1[E1C], g_ssrc2[E2C];

#define NB0 ((N1 + 255) / 256)
#define NB1 ((N2 + 255) / 256)
#define NB2 ((N3 + 255) / 256)

// ---------------- helpers ----------------
__device__ __forceinline__ uint32_t smem_u32(const void* p) {
    uint32_t a;
    asm("{ .reg .u64 t; cvta.to.shared.u64 t, %1; cvt.u32.u64 %0, t; }" : "=r"(a) : "l"(p));
    return a;
}
__device__ __forceinline__ void cp_async16(uint32_t saddr, const void* g, int sz) {
    asm volatile("cp.async.cg.shared.global [%0], [%1], 16, %2;"
                 :: "r"(saddr), "l"(g), "r"(sz) : "memory");
}
__device__ __forceinline__ void cp_commit() {
    asm volatile("cp.async.commit_group;" ::: "memory");
}
template <int N>
__device__ __forceinline__ void cp_wait() {
    asm volatile("cp.async.wait_group %0;" :: "n"(N) : "memory");
}
__device__ __forceinline__ uint32_t pack_h2(float lo, float hi) {
    __half2 h = __floats2half2_rn(lo, hi);
    return *(uint32_t*)&h;
}
__device__ __forceinline__ void acc_h2(float& lo, float& hi, uint32_t u) {
    float2 f = __half22float2(*(const __half2*)&u);
    lo += f.x; hi += f.y;
}
__device__ __forceinline__ void ldm_x4(uint32_t* r, uint32_t addr) {
    asm volatile("ldmatrix.sync.aligned.m8n8.x4.shared.b16 {%0,%1,%2,%3}, [%4];"
                 : "=r"(r[0]), "=r"(r[1]), "=r"(r[2]), "=r"(r[3]) : "r"(addr));
}
__device__ __forceinline__ void mma16n8k16(float& c0, float& c1, float& c2, float& c3,
                                           uint32_t a0, uint32_t a1, uint32_t a2, uint32_t a3,
                                           uint32_t b0, uint32_t b1) {
    asm("mma.sync.aligned.m16n8k16.row.col.f32.f16.f16.f32 "
        "{%0,%1,%2,%3}, {%4,%5,%6,%7}, {%8,%9}, {%0,%1,%2,%3};"
        : "+f"(c0), "+f"(c1), "+f"(c2), "+f"(c3)
        : "r"(a0), "r"(a1), "r"(a2), "r"(a3), "r"(b0), "r"(b1));
}

// ---------------- zero counters (main stream; decoupled from prep) ----------------
__global__ void zero_cnt() {
    int i = blockIdx.x * blockDim.x + threadIdx.x;
    int stride = gridDim.x * blockDim.x;
    for (int j = i; j < N1; j += stride) g_cnt0[j] = 0;
    for (int j = i; j < N2; j += stride) g_cnt1[j] = 0;
    for (int j = i; j < N3; j += stride) g_cnt2[j] = 0;
}

// ---------------- prep: ALL x -> fp16, weights -> [n][kpair] fp16 (side stream) -------
__global__ void prep_kernel(const float* __restrict__ x,
                            const float* __restrict__ Ws0, const float* __restrict__ Wn0,
                            const float* __restrict__ Ws1, const float* __restrict__ Wn1,
                            const float* __restrict__ Ws2, const float* __restrict__ Wn2) {
    int i0 = blockIdx.x * blockDim.x + threadIdx.x;
    int stride = gridDim.x * blockDim.x;
    for (size_t i = i0; i < (size_t)N0 * FIN / 2; i += stride) {
        float2 v = ((const float2*)x)[i];
        g_xh[i] = pack_h2(v.x, v.y);
    }
    for (int i = i0; i < 128 * 256; i += stride) {
        int kp = i >> 8, nn = i & 255;
        float lo, hi;
        if (kp < 64) { lo = Ws0[(2 * kp) * 256 + nn];       hi = Ws0[(2 * kp + 1) * 256 + nn]; }
        else { int q = kp - 64; lo = Wn0[(2 * q) * 256 + nn]; hi = Wn0[(2 * q + 1) * 256 + nn]; }
        g_Wpt0[nn * 128 + kp] = pack_h2(lo, hi);
    }
    for (int i = i0; i < 256 * 256; i += stride) {
        int kp = i >> 8, nn = i & 255;
        float lo, hi;
        if (kp < 128) { lo = Ws1[(2 * kp) * 256 + nn];       hi = Ws1[(2 * kp + 1) * 256 + nn]; }
        else { int q = kp - 128; lo = Wn1[(2 * q) * 256 + nn]; hi = Wn1[(2 * q + 1) * 256 + nn]; }
        g_Wpt1[nn * 256 + kp] = pack_h2(lo, hi);
    }
    for (int i = i0; i < 256 * 64; i += stride) {
        int kp = i >> 6, nn = i & 63;
        float lo = 0.f, hi = 0.f;
        if (nn < FC) {
            if (kp < 128) { lo = Ws2[(2 * kp) * FC + nn];       hi = Ws2[(2 * kp + 1) * FC + nn]; }
            else { int q = kp - 128; lo = Wn2[(2 * q) * FC + nn]; hi = Wn2[(2 * q + 1) * FC + nn]; }
        }
        g_Wpt2[nn * 256 + kp] = pack_h2(lo, hi);
    }
}

// ---------------- histogram ----------------
__global__ void hist_all(const int* __restrict__ d0, int nE0,
                         const int* __restrict__ d1, int nE1,
                         const int* __restrict__ d2, int nE2) {
    int i = blockIdx.x * blockDim.x + threadIdx.x;
    if (i < nE0)                    atomicAdd(&g_cnt0[__ldg(d0 + i)], 1);
    else if (i < nE0 + nE1)         atomicAdd(&g_cnt1[__ldg(d1 + i - nE0)], 1);
    else if (i < nE0 + nE1 + nE2)   atomicAdd(&g_cnt2[__ldg(d2 + i - nE0 - nE1)], 1);
}

// ---------------- scan stage 1: per-block exclusive scan + block sums ----------------
__global__ void scan_block_all() {
    __shared__ int s[256];
    int b = blockIdx.x;
    const int* cnt; int n, lb; int* starts; int* bsum;
    if (b < NB0)            { cnt = g_cnt0; n = N1; starts = g_starts0; bsum = g_bsum0; lb = b; }
    else if (b < NB0 + NB1) { cnt = g_cnt1; n = N2; starts = g_starts1; bsum = g_bsum1; lb = b - NB0; }
    else                    { cnt = g_cnt2; n = N3; starts = g_starts2; bsum = g_bsum2; lb = b - NB0 - NB1; }
    int i = lb * 256 + threadIdx.x;
    int v = (i < n) ? cnt[i] : 0;
    s[threadIdx.x] = v;
    __syncthreads();
    for (int off = 1; off < 256; off <<= 1) {
        int t = (threadIdx.x >= off) ? s[threadIdx.x - off] : 0;
        __syncthreads();
        s[threadIdx.x] += t;
        __syncthreads();
    }
    if (i < n) starts[i] = s[threadIdx.x] - v;
    if (threadIdx.x == 255) bsum[lb] = s[255];
}

// ---------------- scan stage 2 (fused): block-reduce bsum prefix, add ----------------
__global__ void scan_final_all(int nE0, int nE1, int nE2) {
    __shared__ int red[256];
    int b = blockIdx.x;
    int* starts; const int* bsum; int n, nE, lb;
    if (b < NB0)            { starts = g_starts0; bsum = g_bsum0; n = N1; nE = nE0; lb = b; }
    else if (b < NB0 + NB1) { starts = g_starts1; bsum = g_bsum1; n = N2; nE = nE1; lb = b - NB0; }
    else                    { starts = g_starts2; bsum = g_bsum2; n = N3; nE = nE2; lb = b - NB0 - NB1; }
    // offset = sum(bsum[0..lb))
    int p = 0;
    for (int j = threadIdx.x; j < lb; j += 256) p += bsum[j];
    red[threadIdx.x] = p;
    __syncthreads();
    for (int off = 128; off > 0; off >>= 1) {
        if (threadIdx.x < off) red[threadIdx.x] += red[threadIdx.x + off];
        __syncthreads();
    }
    int offv = red[0];
    int i = lb * 256 + threadIdx.x;
    if (i < n) starts[i] += offv;
    if (lb == 0 && threadIdx.x == 0) starts[n] = nE;
}

// ---------------- permute (advances starts; agg recovers via cnt) ----------------
__global__ void permute_all(const int* __restrict__ s0, const int* __restrict__ d0, int nE0,
                            const int* __restrict__ s1, const int* __restrict__ d1, int nE1,
                            const int* __restrict__ s2, const int* __restrict__ d2, int nE2) {
    int i = blockIdx.x * blockDim.x + threadIdx.x;
    if (i < nE0) {
        int d = __ldg(d0 + i);
        g_ssrc0[atomicAdd(&g_starts0[d], 1)] = __ldg(s0 + i);
    } else if (i < nE0 + nE1) {
        int e = i - nE0, d = __ldg(d1 + e);
        g_ssrc1[atomicAdd(&g_starts1[d], 1)] = __ldg(s1 + e);
    } else if (i < nE0 + nE1 + nE2) {
        int e = i - nE0 - nE1, d = __ldg(d2 + e);
        g_ssrc2[atomicAdd(&g_starts2[d], 1)] = __ldg(s2 + e);
    }
}

// ---------------- agg layer0: fp16 gather -> fp16 mean, DIN=128 ----------------
__global__ void agg0_kernel(const uint32_t* __restrict__ xh, const int* __restrict__ ssrc,
                            const int* __restrict__ starts, const int* __restrict__ cnt,
                            uint32_t* __restrict__ mean) {
    constexpr int RW = FIN / 2;
    int w = (int)((blockIdx.x * (unsigned)blockDim.x + threadIdx.x) >> 5);
    int lane = threadIdx.x & 31;
    if (w >= N1) return;
    int end = __ldg(starts + w), c = __ldg(cnt + w), beg = end - c;
    float4 acc = make_float4(0.f, 0.f, 0.f, 0.f);
    int i = beg;
    for (; i + 4 <= end; i += 4) {
        int s0 = __ldg(ssrc + i),     s1 = __ldg(ssrc + i + 1);
        int s2 = __ldg(ssrc + i + 2), s3 = __ldg(ssrc + i + 3);
        uint2 a = __ldg((const uint2*)(xh + (size_t)s0 * RW) + lane);
        uint2 b = __ldg((const uint2*)(xh + (size_t)s1 * RW) + lane);
        uint2 cc = __ldg((const uint2*)(xh + (size_t)s2 * RW) + lane);
        uint2 d = __ldg((const uint2*)(xh + (size_t)s3 * RW) + lane);
        acc_h2(acc.x, acc.y, a.x);  acc_h2(acc.z, acc.w, a.y);
        acc_h2(acc.x, acc.y, b.x);  acc_h2(acc.z, acc.w, b.y);
        acc_h2(acc.x, acc.y, cc.x); acc_h2(acc.z, acc.w, cc.y);
        acc_h2(acc.x, acc.y, d.x);  acc_h2(acc.z, acc.w, d.y);
    }
    for (; i < end; i++) {
        int s0 = __ldg(ssrc + i);
        uint2 a = __ldg((const uint2*)(xh + (size_t)s0 * RW) + lane);
        acc_h2(acc.x, acc.y, a.x);  acc_h2(acc.z, acc.w, a.y);
    }
    float inv = (c > 0) ? (1.0f / (float)c) : 0.0f;
    uint2 o;
    o.x = pack_h2(acc.x * inv, acc.y * inv);
    o.y = pack_h2(acc.z * inv, acc.w * inv);
    *((uint2*)(mean + (size_t)w * RW) + lane) = o;
}

// ---------------- agg layers 1/2: fp16 gather -> fp16 mean, DIN=256 -------------------
__global__ void agg12_kernel(const uint32_t* __restrict__ h, const int* __restrict__ ssrc,
                             const int* __restrict__ starts, const int* __restrict__ cnt,
                             int nD, uint32_t* __restrict__ mean) {
    int w = (int)((blockIdx.x * (unsigned)blockDim.x + threadIdx.x) >> 5);
    int lane = threadIdx.x & 31;
    if (w >= nD) return;
    int end = __ldg(starts + w), c = __ldg(cnt + w), beg = end - c;
    float acc[8];
#pragma unroll
    for (int j = 0; j < 8; j++) acc[j] = 0.f;
    int i = beg;
    for (; i + 2 <= end; i += 2) {
        int s0 = __ldg(ssrc + i), s1 = __ldg(ssrc + i + 1);
        uint4 a = __ldg((const uint4*)(h + (size_t)s0 * (FH / 2)) + lane);
        uint4 b = __ldg((const uint4*)(h + (size_t)s1 * (FH / 2)) + lane);
        acc_h2(acc[0], acc[1], a.x); acc_h2(acc[2], acc[3], a.y);
        acc_h2(acc[4], acc[5], a.z); acc_h2(acc[6], acc[7], a.w);
        acc_h2(acc[0], acc[1], b.x); acc_h2(acc[2], acc[3], b.y);
        acc_h2(acc[4], acc[5], b.z); acc_h2(acc[6], acc[7], b.w);
    }
    if (i < end) {
        int s0 = __ldg(ssrc + i);
        uint4 a = __ldg((const uint4*)(h + (size_t)s0 * (FH / 2)) + lane);
        acc_h2(acc[0], acc[1], a.x); acc_h2(acc[2], acc[3], a.y);
        acc_h2(acc[4], acc[5], a.z); acc_h2(acc[6], acc[7], a.w);
    }
    float inv = (c > 0) ? (1.0f / (float)c) : 0.0f;
    uint4 o;
    o.x = pack_h2(acc[0] * inv, acc[1] * inv);
    o.y = pack_h2(acc[2] * inv, acc[3] * inv);
    o.z = pack_h2(acc[4] * inv, acc[5] * inv);
    o.w = pack_h2(acc[6] * inv, acc[7] * inv);
    *((uint4*)(mean + (size_t)w * (FH / 2)) + lane) = o;
}

// ---------------- GEMM: cp.async + ldmatrix + m16n8k16 fp16 ----------------
template <int K, int DOUTP, bool FINAL>
__global__ void __launch_bounds__(256, 2)
sage_gemm(const uint32_t* __restrict__ selfp, const uint32_t* __restrict__ meanp,
          const uint32_t* __restrict__ Wpt, const float* __restrict__ bias,
          void* __restrict__ Cout, int n, int dout) {
    constexpr int KP    = K / 2;
    constexpr int DINKP = K / 4;
    constexpr int SROW  = K / 4;
    constexpr int NCH   = KP / 32;
    constexpr int ST    = 36;
    constexpr int TEL   = 128 * ST;
    extern __shared__ uint32_t smem[];
    uint32_t* sA[2] = { smem, smem + TEL };
    uint32_t* sB[2] = { smem + 2 * TEL, smem + 3 * TEL };
    const uint32_t sA32[2] = { smem_u32(sA[0]), smem_u32(sA[1]) };
    const uint32_t sB32[2] = { smem_u32(sB[0]), smem_u32(sB[1]) };

    const int tid  = threadIdx.x;
    const int lane = tid & 31, wid = tid >> 5;
    const int gid  = lane >> 2, tig = lane & 3;
    const int row0 = blockIdx.x * 128, col0 = blockIdx.y * 128;
    const int wr = wid & 3, wc = wid >> 2;

    const int aOff = (lane & 15) * ST + ((lane >> 4) << 2);
    const int bOff = ((lane & 7) | ((lane & 16) >> 1)) * ST + (((lane >> 3) & 1) << 2);

    auto issue = [&](int kc, int buf) {
        const int kp0 = kc * 32;
        const uint32_t* base = (kp0 < DINKP) ? selfp : meanp;
        const int kpl = (kp0 < DINKP) ? kp0 : (kp0 - DINKP);
#pragma unroll
        for (int it = 0; it < 4; it++) {
            int f = tid + it * 256;
            int r = f >> 3, seg = f & 7;
            bool ok = (row0 + r) < n;
            const uint32_t* g = base + (ok ? ((size_t)(row0 + r) * SROW + kpl + seg * 4) : 0);
            cp_async16(sA32[buf] + (uint32_t)(r * ST + seg * 4) * 4u, g, ok ? 16 : 0);
        }
#pragma unroll
        for (int it = 0; it < 4; it++) {
            int f = tid + it * 256;
            int r = f >> 3, seg = f & 7;
            bool ok = (col0 + r) < DOUTP;
            const uint32_t* g = Wpt + (ok ? ((size_t)(col0 + r) * KP + kp0 + seg * 4) : 0);
            cp_async16(sB32[buf] + (uint32_t)(r * ST + seg * 4) * 4u, g, ok ? 16 : 0);
        }
        cp_commit();
    };

    float acc[2][8][4];
#pragma unroll
    for (int mi = 0; mi < 2; mi++)
#pragma unroll
        for (int ni = 0; ni < 8; ni++)
#pragma unroll
            for (int j = 0; j < 4; j++) acc[mi][ni][j] = 0.f;

    issue(0, 0);
    for (int kc = 0; kc < NCH; kc++) {
        const int buf = kc & 1;
        if (kc + 1 < NCH) { issue(kc + 1, buf ^ 1); cp_wait<1>(); }
        else              { cp_wait<0>(); }
        __syncthreads();
        const uint32_t aBase = sA32[buf] + (uint32_t)(wr * 32 * ST + aOff) * 4u;
        const uint32_t bBase = sB32[buf] + (uint32_t)(wc * 64 * ST + bOff) * 4u;
#pragma unroll
        for (int ks = 0; ks < 4; ks++) {
            const uint32_t kbB = (uint32_t)(ks * 8) * 4u;
            uint32_t a[2][4];
#pragma unroll
            for (int mi = 0; mi < 2; mi++)
                ldm_x4(a[mi], aBase + (uint32_t)(mi * 16 * ST) * 4u + kbB);
#pragma unroll
            for (int nj = 0; nj < 4; nj++) {
                uint32_t b[4];
                ldm_x4(b, bBase + (uint32_t)(nj * 16 * ST) * 4u + kbB);
#pragma unroll
                for (int mi = 0; mi < 2; mi++) {
                    mma16n8k16(acc[mi][2 * nj][0], acc[mi][2 * nj][1],
                               acc[mi][2 * nj][2], acc[mi][2 * nj][3],
                               a[mi][0], a[mi][1], a[mi][2], a[mi][3], b[0], b[1]);
                    mma16n8k16(acc[mi][2 * nj + 1][0], acc[mi][2 * nj + 1][1],
                               acc[mi][2 * nj + 1][2], acc[mi][2 * nj + 1][3],
                               a[mi][0], a[mi][1], a[mi][2], a[mi][3], b[2], b[3]);
                }
            }
        }
        __syncthreads();
    }

#pragma unroll
    for (int mi = 0; mi < 2; mi++) {
        int row = row0 + wr * 32 + mi * 16 + gid;
#pragma unroll
        for (int ni = 0; ni < 8; ni++) {
            int col = col0 + wc * 64 + ni * 8 + tig * 2;
#pragma unroll
            for (int half = 0; half < 2; half++) {
                int r = row + half * 8;
                if (r >= n) continue;
                float v0 = acc[mi][ni][half * 2 + 0];
                float v1 = acc[mi][ni][half * 2 + 1];
                if (FINAL) {
                    float* o = (float*)Cout;
                    if (col < dout)     o[(size_t)r * dout + col]     = v0 + __ldg(bias + col);
                    if (col + 1 < dout) o[(size_t)r * dout + col + 1] = v1 + __ldg(bias + col + 1);
                } else {
                    v0 = fmaxf(v0 + __ldg(bias + col), 0.f);
                    v1 = fmaxf(v1 + __ldg(bias + col + 1), 0.f);
                    ((uint32_t*)Cout)[(size_t)r * (DOUTP / 2) + (col >> 1)] = pack_h2(v0, v1);
                }
            }
        }
    }
}

// ---------------- host launcher ----------------
extern "C" void kernel_launch(void* const* d_in, const int* in_sizes, int n_in,
                              void* d_out, int out_size) {
    const float* x    = (const float*)d_in[0];
    const int*   src0 = (const int*)d_in[1];
    const int*   dst0 = (const int*)d_in[2];
    const int*   src1 = (const int*)d_in[3];
    const int*   dst1 = (const int*)d_in[4];
    const int*   src2 = (const int*)d_in[5];
    const int*   dst2 = (const int*)d_in[6];
    const float* Ws0  = (const float*)d_in[7];
    const float* Wn0  = (const float*)d_in[8];
    const float* b0   = (const float*)d_in[9];
    const float* Ws1  = (const float*)d_in[10];
    const float* Wn1  = (const float*)d_in[11];
    const float* b1   = (const float*)d_in[12];
    const float* Ws2  = (const float*)d_in[13];
    const float* Wn2  = (const float*)d_in[14];
    const float* b2   = (const float*)d_in[15];
    float* out = (float*)d_out;

    int E0 = in_sizes[1], E1 = in_sizes[3], E2 = in_sizes[5];
    int ET = E0 + E1 + E2;

    uint32_t *xh, *mean0, *h1, *mean1, *h2, *mean2, *Wpt0, *Wpt1, *Wpt2;
    int *st0, *st1, *st2, *cn0, *cn1, *cn2, *ss0, *ss1, *ss2;
    cudaGetSymbolAddress((void**)&xh, g_xh);
    cudaGetSymbolAddress((void**)&mean0, g_mean0);
    cudaGetSymbolAddress((void**)&h1, g_h1);
    cudaGetSymbolAddress((void**)&mean1, g_mean1);
    cudaGetSymbolAddress((void**)&h2, g_h2);
    cudaGetSymbolAddress((void**)&mean2, g_mean2);
    cudaGetSymbolAddress((void**)&Wpt0, g_Wpt0);
    cudaGetSymbolAddress((void**)&Wpt1, g_Wpt1);
    cudaGetSymbolAddress((void**)&Wpt2, g_Wpt2);
    cudaGetSymbolAddress((void**)&st0, g_starts0);
    cudaGetSymbolAddress((void**)&st1, g_starts1);
    cudaGetSymbolAddress((void**)&st2, g_starts2);
    cudaGetSymbolAddress((void**)&cn0, g_cnt0);
    cudaGetSymbolAddress((void**)&cn1, g_cnt1);
    cudaGetSymbolAddress((void**)&cn2, g_cnt2);
    cudaGetSymbolAddress((void**)&ss0, g_ssrc0);
    cudaGetSymbolAddress((void**)&ss1, g_ssrc1);
    cudaGetSymbolAddress((void**)&ss2, g_ssrc2);

    const int SMEM = 4 * 128 * 36 * 4;   // 73728 B
    cudaFuncSetAttribute(sage_gemm<256, 256, false>,
                         cudaFuncAttributeMaxDynamicSharedMemorySize, SMEM);
    cudaFuncSetAttribute(sage_gemm<512, 256, false>,
                         cudaFuncAttributeMaxDynamicSharedMemorySize, SMEM);
    cudaFuncSetAttribute(sage_gemm<512, 64, true>,
                         cudaFuncAttributeMaxDynamicSharedMemorySize, SMEM);

    // side stream + events (created once, outside capture; reused each call)
    static cudaStream_t sSide = nullptr;
    static cudaEvent_t evF, evJ;
    if (!sSide) {
        cudaStreamCreateWithFlags(&sSide, cudaStreamNonBlocking);
        cudaEventCreateWithFlags(&evF, cudaEventDisableTiming);
        cudaEventCreateWithFlags(&evJ, cudaEventDisableTiming);
    }

    // ==== fork: prep (streaming, side) || sort chain (latency-bound, main) ====
    cudaEventRecord(evF, 0);
    cudaStreamWaitEvent(sSide, evF, 0);
    prep_kernel<<<1184, 256, 0, sSide>>>(x, Ws0, Wn0, Ws1, Wn1, Ws2, Wn2);
    cudaEventRecord(evJ, sSide);

    zero_cnt<<<160, 256>>>();
    hist_all<<<(ET + 255) / 256, 256>>>(dst0, E0, dst1, E1, dst2, E2);
    scan_block_all<<<NB0 + NB1 + NB2, 256>>>();
    scan_final_all<<<NB0 + NB1 + NB2, 256>>>(E0, E1, E2);
    permute_all<<<(ET + 255) / 256, 256>>>(src0, dst0, E0, src1, dst1, E1, src2, dst2, E2);

    // join: agg0 needs g_xh (side) + ssrc/starts (main)
    cudaStreamWaitEvent(0, evJ, 0);

    // ---- layer 0 ----
    agg0_kernel<<<(N1 * 32 + 255) / 256, 256>>>(xh, ss0, st0, cn0, mean0);
    sage_gemm<256, 256, false><<<dim3((N1 + 127) / 128, 2), 256, SMEM>>>(
        xh, mean0, Wpt0, b0, h1, N1, FH);

    // ---- layer 1 ----
    agg12_kernel<<<(N2 * 32 + 255) / 256, 256>>>(h1, ss1, st1, cn1, N2, mean1);
    sage_gemm<512, 256, false><<<dim3((N2 + 127) / 128, 2), 256, SMEM>>>(
        h1, mean1, Wpt1, b1, h2, N2, FH);

    // ---- layer 2 ----
    agg12_kernel<<<(N3 * 32 + 255) / 256, 256>>>(h2, ss2, st2, cn2, N3, mean2);
    sage_gemm<512, 64, true><<<dim3((N3 + 127) / 128, 1), 256, SMEM>>>(
        h2, mean2, Wpt2, b2, out, N3, FC);
}